// round 2
// baseline (speedup 1.0000x reference)
#include <cuda_runtime.h>
#include <math.h>

#define Bb 128
#define Nn 128
#define Ss 128
#define Ee 300
#define Tt 255

// Scratch (static device allocations are the sanctioned way to get scratch)
__device__ float g_buffer[Bb * Nn * 2 * Ss];   // 16 MB: embedded+projected tokens
__device__ float g_stack [Bb * Nn * 2 * Ss];   // 16 MB: per-batch stacks
__device__ float g_loss  [Bb];

__device__ __forceinline__ float sigf(float x) { return 1.0f / (1.0f + expf(-x)); }

// ---------------------------------------------------------------------------
// Kernel 1: buffer[b,n,:] = embed_table[tokens[b,n]] @ W_proj   ([300] x [300,256])
// 16 tokens per block, 256 threads: thread = output column, 16 row-accumulators.
// ---------------------------------------------------------------------------
__global__ void __launch_bounds__(256) embed_kernel(
    const int*   __restrict__ tokens,
    const float* __restrict__ embed_table,
    const float* __restrict__ W_proj)
{
    __shared__ float se[16 * Ee];
    __shared__ int   stok[16];
    const int blk = blockIdx.x;          // 1024 blocks * 16 tokens = 16384
    const int tid = threadIdx.x;

    if (tid < 16) stok[tid] = tokens[blk * 16 + tid];
    __syncthreads();
    for (int idx = tid; idx < 16 * Ee; idx += 256) {
        int j = idx / Ee, e = idx - j * Ee;
        se[idx] = embed_table[(size_t)stok[j] * Ee + e];
    }
    __syncthreads();

    const int col = tid;                 // 0..255
    float acc[16];
#pragma unroll
    for (int j = 0; j < 16; j++) acc[j] = 0.0f;

    for (int e = 0; e < Ee; e++) {
        float w = W_proj[e * 256 + col];
#pragma unroll
        for (int j = 0; j < 16; j++) acc[j] += se[j * Ee + e] * w;
    }
#pragma unroll
    for (int j = 0; j < 16; j++)
        g_buffer[(size_t)(blk * 16 + j) * 256 + col] = acc[j];
}

// ---------------------------------------------------------------------------
// Kernel 2: the sequential SPINN scan. One CTA per batch element, 256 threads.
// All state (stack, h, c, ptr, bptr) is CTA-local; no inter-CTA dependencies.
// ---------------------------------------------------------------------------
__global__ void __launch_bounds__(256) spinn_seq(
    const int*   __restrict__ transitions,   // [B, T]
    const float* __restrict__ W_buf,  const float* __restrict__ W_s1,
    const float* __restrict__ W_s2,   const float* __restrict__ W_lat,
    const float* __restrict__ b_lat,
    const float* __restrict__ W_trans,const float* __restrict__ b_trans,
    const float* __restrict__ W_left, const float* __restrict__ W_right,
    const float* __restrict__ W_track,const float* __restrict__ b_reduce,
    float* __restrict__ out_final)
{
    const int b   = blockIdx.x;
    const int tid = threadIdx.x;

    __shared__ float bt[256], s1[256], s2[256];   // gathered buf_top / stack top-2
    __shared__ float hs[128], cs[128];            // tracker LSTM state
    __shared__ float lstm[512];                   // tracker pre-activations
    __shared__ float gg[640];                     // TreeLSTM pre-activations
    __shared__ float red[256];                    // reduced = [h_new | c_new]
    __shared__ float r0[128], r1[128];            // logits reduction scratch
    __shared__ float loss_s;

    if (tid < 128) { hs[tid] = 0.0f; cs[tid] = 0.0f; }
    if (tid == 0)  loss_s = 0.0f;

    int ptr = 0, bptr = 0;                        // uniform across the CTA
    float* stck = g_stack  + (size_t)b * Nn * 256;
    const float* buf = g_buffer + (size_t)b * Nn * 256;
    __syncthreads();

    for (int t = 0; t < Tt; t++) {
        const int tr = transitions[b * Tt + t];   // 0 = shift, 1 = reduce

        // ---- gather buf_top, s1 (top), s2 (second) with presence masking ----
        const int  btop = (bptr < Nn - 1) ? bptr : (Nn - 1);
        const int  i1 = (ptr - 1 >= 0) ? ptr - 1 : 0;
        const int  i2 = (ptr - 2 >= 0) ? ptr - 2 : 0;
        const bool h1 = (ptr >= 1), h2 = (ptr >= 2);
        {
            const int i = tid;                    // 256 threads cover 256 elems
            bt[i] = buf[btop * 256 + i];
            s1[i] = h1 ? stck[i1 * 256 + i] : 0.0f;
            s2[i] = h2 ? stck[i2 * 256 + i] : 0.0f;
        }
        __syncthreads();

        // ---- tracker pre-activation: [512] = bt_h@W_buf + s1_h@W_s1 + s2_h@W_s2 + h@W_lat (+ b_lat if t>0)
        for (int c = tid; c < 512; c += 256) {
            float acc = (t == 0) ? 0.0f : b_lat[c];
#pragma unroll 4
            for (int k = 0; k < 128; k++) {
                acc += bt[k] * W_buf[k * 512 + c];
                acc += s1[k] * W_s1 [k * 512 + c];
                acc += s2[k] * W_s2 [k * 512 + c];
                acc += hs[k] * W_lat[k * 512 + c];
            }
            lstm[c] = acc;
        }
        __syncthreads();

        // ---- tracker LSTM cell + logit partials ----
        if (tid < 128) {
            float a  = lstm[tid], ii = lstm[128 + tid];
            float f  = lstm[256 + tid], o = lstm[384 + tid];
            float cn = sigf(f) * cs[tid] + sigf(ii) * tanhf(a);
            float hn = sigf(o) * tanhf(cn);
            cs[tid] = cn; hs[tid] = hn;
            r0[tid] = hn * W_trans[tid * 2 + 0];
            r1[tid] = hn * W_trans[tid * 2 + 1];
        }
        __syncthreads();

        // ---- logits reduce + cross-entropy accumulation ----
        for (int off = 64; off > 0; off >>= 1) {
            if (tid < off) { r0[tid] += r0[tid + off]; r1[tid] += r1[tid + off]; }
            __syncthreads();
        }
        if (tid == 0) {
            float l0 = r0[0] + b_trans[0], l1 = r1[0] + b_trans[1];
            float m  = fmaxf(l0, l1);
            float lse = m + logf(expf(l0 - m) + expf(l1 - m));
            float ltgt = (tr == 0) ? l0 : l1;
            loss_s += (lse - ltgt);                 // = -logp[target]
        }

        // ---- TreeLSTM pre-activation: right = s1, left = s2 ----
        for (int c = tid; c < 640; c += 256) {
            float acc = b_reduce[c];
#pragma unroll 4
            for (int k = 0; k < 128; k++) {
                acc += s2[k] * W_left [k * 640 + c];   // left  = s2
                acc += s1[k] * W_right[k * 640 + c];   // right = s1
                acc += hs[k] * W_track[k * 640 + c];   // NEW h
            }
            gg[c] = acc;
        }
        __syncthreads();

        // ---- TreeLSTM composition ----
        if (tid < 128) {
            float a2 = gg[tid],        i2 = gg[128 + tid];
            float f1 = gg[256 + tid],  f2 = gg[384 + tid], o2 = gg[512 + tid];
            float cn = tanhf(a2) * sigf(i2)
                     + sigf(f1) * s2[128 + tid]        // left[:, S:]
                     + sigf(f2) * s1[128 + tid];       // right[:, S:]
            float hn = sigf(o2) * tanhf(cn);
            red[tid] = hn; red[128 + tid] = cn;
        }
        __syncthreads();

        // ---- apply transition ----
        const bool shift = (tr == 0);
        int wpos = shift ? ptr : ((ptr - 2 >= 0) ? ptr - 2 : 0);
        if (wpos > Nn - 1) wpos = Nn - 1;
        if (wpos < 0) wpos = 0;
        stck[wpos * 256 + tid] = shift ? bt[tid] : red[tid];
        ptr  += shift ? 1 : -1;
        bptr += shift ? 1 : 0;
        __syncthreads();   // stack write visible before next gather
    }

    // ---- final = stack top ----
    int fin = (ptr - 1 >= 0) ? ptr - 1 : 0;
    if (fin > Nn - 1) fin = Nn - 1;
    out_final[b * 256 + tid] = stck[fin * 256 + tid];
    if (tid == 0) g_loss[b] = loss_s;
}

// ---------------------------------------------------------------------------
// Kernel 3: reduce per-batch loss sums -> scalar at d_out[out_size-1]
// ---------------------------------------------------------------------------
__global__ void loss_kernel(float* __restrict__ out, int loss_idx)
{
    __shared__ float sl[128];
    int tid = threadIdx.x;
    sl[tid] = g_loss[tid];
    __syncthreads();
    for (int off = 64; off > 0; off >>= 1) {
        if (tid < off) sl[tid] += sl[tid + off];
        __syncthreads();
    }
    if (tid == 0) out[loss_idx] = sl[0] / (float)(Tt * Bb);
}

// ---------------------------------------------------------------------------
extern "C" void kernel_launch(void* const* d_in, const int* in_sizes, int n_in,
                              void* d_out, int out_size)
{
    const int*   tokens      = (const int*)  d_in[0];
    const int*   transitions = (const int*)  d_in[1];
    const float* embed_table = (const float*)d_in[2];
    const float* W_proj      = (const float*)d_in[3];
    const float* W_buf       = (const float*)d_in[4];
    const float* W_s1        = (const float*)d_in[5];
    const float* W_s2        = (const float*)d_in[6];
    const float* W_lat       = (const float*)d_in[7];
    const float* b_lat       = (const float*)d_in[8];
    const float* W_trans     = (const float*)d_in[9];
    const float* b_trans     = (const float*)d_in[10];
    const float* W_left      = (const float*)d_in[11];
    const float* W_right     = (const float*)d_in[12];
    const float* W_track     = (const float*)d_in[13];
    const float* b_reduce    = (const float*)d_in[14];
    float* out = (float*)d_out;

    embed_kernel<<<(Bb * Nn) / 16, 256>>>(tokens, embed_table, W_proj);
    spinn_seq<<<Bb, 256>>>(transitions,
                           W_buf, W_s1, W_s2, W_lat, b_lat,
                           W_trans, b_trans,
                           W_left, W_right, W_track, b_reduce,
                           out);
    loss_kernel<<<1, 128>>>(out, out_size - 1);
}

// round 3
// speedup vs baseline: 1.2696x; 1.2696x over previous
#include <cuda_runtime.h>
#include <math.h>

#define Bb 128
#define Nn 128
#define Ss 128
#define Ee 300
#define Tt 255
#define GPB 4                      // batch elements per CTA
#define NGRP (Bb / GPB)            // 32 CTAs

__device__ float g_buffer[Bb * Nn * 2 * Ss];   // 16 MB: embedded+projected tokens
__device__ float g_stack [Bb * Nn * 2 * Ss];   // 16 MB: per-batch stacks
__device__ float g_loss  [Bb];

__device__ __forceinline__ float sigf(float x) { return 1.0f / (1.0f + expf(-x)); }

// ---------------------------------------------------------------------------
// Kernel 1: buffer[b,n,:] = embed_table[tokens[b,n]] @ W_proj  ([300]x[300,256])
// ---------------------------------------------------------------------------
__global__ void __launch_bounds__(256) embed_kernel(
    const int*   __restrict__ tokens,
    const float* __restrict__ embed_table,
    const float* __restrict__ W_proj)
{
    __shared__ float se[16 * Ee];
    __shared__ int   stok[16];
    const int blk = blockIdx.x;
    const int tid = threadIdx.x;

    if (tid < 16) stok[tid] = tokens[blk * 16 + tid];
    __syncthreads();
    for (int idx = tid; idx < 16 * Ee; idx += 256) {
        int j = idx / Ee, e = idx - j * Ee;
        se[idx] = embed_table[(size_t)stok[j] * Ee + e];
    }
    __syncthreads();

    const int col = tid;
    float acc[16];
#pragma unroll
    for (int j = 0; j < 16; j++) acc[j] = 0.0f;
    for (int e = 0; e < Ee; e++) {
        float w = W_proj[e * 256 + col];
#pragma unroll
        for (int j = 0; j < 16; j++) acc[j] += se[j * Ee + e] * w;
    }
#pragma unroll
    for (int j = 0; j < 16; j++)
        g_buffer[(size_t)(blk * 16 + j) * 256 + col] = acc[j];
}

// ---------------------------------------------------------------------------
// Kernel 2: sequential scan. 32 CTAs, each owns 4 batch elements.
// Weight values are loaded once per CTA and reused across 4 batch accumulators.
// Tree-LSTM GEMM is skipped on steps where all 4 batches shift.
// ---------------------------------------------------------------------------
__global__ void __launch_bounds__(256, 1) spinn_seq(
    const int*   __restrict__ transitions,   // [B, T]
    const float* __restrict__ W_buf,  const float* __restrict__ W_s1,
    const float* __restrict__ W_s2,   const float* __restrict__ W_lat,
    const float* __restrict__ b_lat,
    const float* __restrict__ W_trans,const float* __restrict__ b_trans,
    const float* __restrict__ W_left, const float* __restrict__ W_right,
    const float* __restrict__ W_track,const float* __restrict__ b_reduce,
    float* __restrict__ out_final)
{
    const int grp = blockIdx.x;       // 0..31
    const int tid = threadIdx.x;
    const int b0  = grp * GPB;

    __shared__ float bt[GPB][256], s1[GPB][256], s2[GPB][256];
    __shared__ float hs[GPB][128], cs[GPB][128];
    __shared__ float lstm[GPB][512];
    __shared__ float gg[GPB][640];
    __shared__ float sloss[GPB];
    __shared__ int   str[GPB][Tt];    // cached transitions

    for (int i = tid; i < GPB * 128; i += 256) {
        int g = i >> 7, j = i & 127;
        hs[g][j] = 0.0f; cs[g][j] = 0.0f;
    }
    if (tid < GPB) sloss[tid] = 0.0f;
    for (int i = tid; i < GPB * Tt; i += 256) {
        int g = i / Tt, t = i - g * Tt;
        str[g][t] = transitions[(b0 + g) * Tt + t];
    }

    int ptr_[GPB], bptr_[GPB];
#pragma unroll
    for (int g = 0; g < GPB; g++) { ptr_[g] = 0; bptr_[g] = 0; }

    float*       stck = g_stack  + (size_t)b0 * Nn * 256;
    const float* buf  = g_buffer + (size_t)b0 * Nn * 256;
    __syncthreads();

    for (int t = 0; t < Tt; t++) {
        int tr[GPB];
#pragma unroll
        for (int g = 0; g < GPB; g++) tr[g] = str[g][t];
        const bool any_red = (tr[0] | tr[1] | tr[2] | tr[3]) != 0;

        // ---------------- gather: bt, s1, s2 (float4, masked) ----------------
        {
            const int g = tid >> 6;
            const int e = (tid & 63) * 4;
            const int btop = (bptr_[g] < Nn - 1) ? bptr_[g] : (Nn - 1);
            const int i1 = (ptr_[g] - 1 >= 0) ? ptr_[g] - 1 : 0;
            const int i2 = (ptr_[g] - 2 >= 0) ? ptr_[g] - 2 : 0;
            const float4 z = make_float4(0.f, 0.f, 0.f, 0.f);
            *(float4*)&bt[g][e] = *(const float4*)&buf[((size_t)g * Nn + btop) * 256 + e];
            *(float4*)&s1[g][e] = (ptr_[g] >= 1) ?
                *(const float4*)&stck[((size_t)g * Nn + i1) * 256 + e] : z;
            *(float4*)&s2[g][e] = (ptr_[g] >= 2) ?
                *(const float4*)&stck[((size_t)g * Nn + i2) * 256 + e] : z;
        }
        __syncthreads();

        // ---------------- tracker GEMM: 512 cols, thread owns col pair -------
        {
            const int c = tid * 2;
            float acc[GPB][2];
            float2 bl = (t == 0) ? make_float2(0.f, 0.f)
                                 : *(const float2*)&b_lat[c];
#pragma unroll
            for (int g = 0; g < GPB; g++) { acc[g][0] = bl.x; acc[g][1] = bl.y; }

            for (int k = 0; k < 128; k += 4) {
                float a_bt[GPB][4], a_s1[GPB][4], a_s2[GPB][4], a_h[GPB][4];
#pragma unroll
                for (int g = 0; g < GPB; g++) {
                    float4 v;
                    v = *(const float4*)&bt[g][k];
                    a_bt[g][0]=v.x; a_bt[g][1]=v.y; a_bt[g][2]=v.z; a_bt[g][3]=v.w;
                    v = *(const float4*)&s1[g][k];
                    a_s1[g][0]=v.x; a_s1[g][1]=v.y; a_s1[g][2]=v.z; a_s1[g][3]=v.w;
                    v = *(const float4*)&s2[g][k];
                    a_s2[g][0]=v.x; a_s2[g][1]=v.y; a_s2[g][2]=v.z; a_s2[g][3]=v.w;
                    v = *(const float4*)&hs[g][k];
                    a_h [g][0]=v.x; a_h [g][1]=v.y; a_h [g][2]=v.z; a_h [g][3]=v.w;
                }
#pragma unroll
                for (int kk = 0; kk < 4; kk++) {
                    const int row = (k + kk) * 512 + c;
                    const float2 wb = *(const float2*)&W_buf[row];
                    const float2 w1 = *(const float2*)&W_s1 [row];
                    const float2 w2 = *(const float2*)&W_s2 [row];
                    const float2 wl = *(const float2*)&W_lat[row];
#pragma unroll
                    for (int g = 0; g < GPB; g++) {
                        acc[g][0] += a_bt[g][kk]*wb.x + a_s1[g][kk]*w1.x
                                   + a_s2[g][kk]*w2.x + a_h [g][kk]*wl.x;
                        acc[g][1] += a_bt[g][kk]*wb.y + a_s1[g][kk]*w1.y
                                   + a_s2[g][kk]*w2.y + a_h [g][kk]*wl.y;
                    }
                }
            }
#pragma unroll
            for (int g = 0; g < GPB; g++)
                *(float2*)&lstm[g][c] = make_float2(acc[g][0], acc[g][1]);
        }
        __syncthreads();

        // ---------------- tracker LSTM cell ----------------
        for (int idx = tid; idx < GPB * 128; idx += 256) {
            int g = idx >> 7, j = idx & 127;
            float a  = lstm[g][j],       ii = lstm[g][128 + j];
            float f  = lstm[g][256 + j], o  = lstm[g][384 + j];
            float cn = sigf(f) * cs[g][j] + sigf(ii) * tanhf(a);
            float hn = sigf(o) * tanhf(cn);
            cs[g][j] = cn; hs[g][j] = hn;
        }
        __syncthreads();

        // ------- phase X: logits (warps 0-3)  +  tree GEMM (if any reduce) ----
        if (tid < 128) {
            int g = tid >> 5, l = tid & 31;
            float p0 = 0.f, p1 = 0.f;
#pragma unroll
            for (int jj = 0; jj < 4; jj++) {
                int j = l + 32 * jj;
                float h = hs[g][j];
                p0 += h * W_trans[2 * j];
                p1 += h * W_trans[2 * j + 1];
            }
#pragma unroll
            for (int off = 16; off > 0; off >>= 1) {
                p0 += __shfl_xor_sync(0xffffffffu, p0, off);
                p1 += __shfl_xor_sync(0xffffffffu, p1, off);
            }
            if (l == 0) {
                float l0 = p0 + b_trans[0], l1 = p1 + b_trans[1];
                float m  = fmaxf(l0, l1);
                float lse = m + logf(expf(l0 - m) + expf(l1 - m));
                sloss[g] += lse - ((tr[g] == 0) ? l0 : l1);
            }
        }

        if (any_red) {
            // tree GEMM: 640 cols = 320 pairs. pair1 = tid (all threads),
            // pair2 = 256 + (tid-192) for warps 6,7 (disjoint from logit warps).
            const int c1 = tid * 2;
            const bool xtra = (tid >= 192);
            const int c2 = (256 + (tid - 192)) * 2;
            float acc1[GPB][2], acc2[GPB][2];
            {
                float2 br1 = *(const float2*)&b_reduce[c1];
#pragma unroll
                for (int g = 0; g < GPB; g++) { acc1[g][0]=br1.x; acc1[g][1]=br1.y; }
                if (xtra) {
                    float2 br2 = *(const float2*)&b_reduce[c2];
#pragma unroll
                    for (int g = 0; g < GPB; g++) { acc2[g][0]=br2.x; acc2[g][1]=br2.y; }
                }
            }
            for (int k = 0; k < 128; k += 4) {
                float a_l[GPB][4], a_r[GPB][4], a_h[GPB][4];
#pragma unroll
                for (int g = 0; g < GPB; g++) {
                    float4 v;
                    v = *(const float4*)&s2[g][k];   // left  = s2
                    a_l[g][0]=v.x; a_l[g][1]=v.y; a_l[g][2]=v.z; a_l[g][3]=v.w;
                    v = *(const float4*)&s1[g][k];   // right = s1
                    a_r[g][0]=v.x; a_r[g][1]=v.y; a_r[g][2]=v.z; a_r[g][3]=v.w;
                    v = *(const float4*)&hs[g][k];
                    a_h[g][0]=v.x; a_h[g][1]=v.y; a_h[g][2]=v.z; a_h[g][3]=v.w;
                }
#pragma unroll
                for (int kk = 0; kk < 4; kk++) {
                    const int rowb = (k + kk) * 640;
                    const float2 wl = *(const float2*)&W_left [rowb + c1];
                    const float2 wr = *(const float2*)&W_right[rowb + c1];
                    const float2 wt = *(const float2*)&W_track[rowb + c1];
#pragma unroll
                    for (int g = 0; g < GPB; g++) {
                        acc1[g][0] += a_l[g][kk]*wl.x + a_r[g][kk]*wr.x + a_h[g][kk]*wt.x;
                        acc1[g][1] += a_l[g][kk]*wl.y + a_r[g][kk]*wr.y + a_h[g][kk]*wt.y;
                    }
                    if (xtra) {
                        const float2 wl2 = *(const float2*)&W_left [rowb + c2];
                        const float2 wr2 = *(const float2*)&W_right[rowb + c2];
                        const float2 wt2 = *(const float2*)&W_track[rowb + c2];
#pragma unroll
                        for (int g = 0; g < GPB; g++) {
                            acc2[g][0] += a_l[g][kk]*wl2.x + a_r[g][kk]*wr2.x + a_h[g][kk]*wt2.x;
                            acc2[g][1] += a_l[g][kk]*wl2.y + a_r[g][kk]*wr2.y + a_h[g][kk]*wt2.y;
                        }
                    }
                }
            }
#pragma unroll
            for (int g = 0; g < GPB; g++)
                *(float2*)&gg[g][c1] = make_float2(acc1[g][0], acc1[g][1]);
            if (xtra) {
#pragma unroll
                for (int g = 0; g < GPB; g++)
                    *(float2*)&gg[g][c2] = make_float2(acc2[g][0], acc2[g][1]);
            }
        }
        __syncthreads();

        // ------- compose (reduce batches) + stack write + pointer update ------
        for (int idx = tid; idx < GPB * 128; idx += 256) {
            int g = idx >> 7, j = idx & 127;
            bool sh = (tr[g] == 0);
            int wp = sh ? ptr_[g] : ((ptr_[g] - 2 >= 0) ? ptr_[g] - 2 : 0);
            if (wp < 0) wp = 0;
            if (wp > Nn - 1) wp = Nn - 1;
            float v0, v1;
            if (sh) {
                v0 = bt[g][j]; v1 = bt[g][128 + j];
            } else {
                float a2 = gg[g][j],        i2 = gg[g][128 + j];
                float f1 = gg[g][256 + j],  f2 = gg[g][384 + j], o2 = gg[g][512 + j];
                float cn = tanhf(a2) * sigf(i2)
                         + sigf(f1) * s2[g][128 + j]     // left[:, S:]
                         + sigf(f2) * s1[g][128 + j];    // right[:, S:]
                v1 = cn; v0 = sigf(o2) * tanhf(cn);
            }
            stck[((size_t)g * Nn + wp) * 256 + j]       = v0;
            stck[((size_t)g * Nn + wp) * 256 + 128 + j] = v1;
        }
#pragma unroll
        for (int g = 0; g < GPB; g++) {
            bool sh = (tr[g] == 0);
            ptr_[g]  += sh ? 1 : -1;
            bptr_[g] += sh ? 1 : 0;
        }
        __syncthreads();   // stack write visible before next gather
    }

    // ---------------- final = stack top, per batch ----------------
    {
        const int g = tid >> 6;
        const int e = (tid & 63) * 4;
        int fin = (ptr_[g] - 1 >= 0) ? ptr_[g] - 1 : 0;
        if (fin > Nn - 1) fin = Nn - 1;
        float4 v = *(const float4*)&stck[((size_t)g * Nn + fin) * 256 + e];
        *(float4*)&out_final[(size_t)(b0 + g) * 256 + e] = v;
    }
    if (tid < GPB) g_loss[b0 + tid] = sloss[tid];
}

// ---------------------------------------------------------------------------
// Kernel 3: reduce per-batch loss sums -> scalar at d_out[out_size-1]
// ---------------------------------------------------------------------------
__global__ void loss_kernel(float* __restrict__ out, int loss_idx)
{
    __shared__ float sl[128];
    int tid = threadIdx.x;
    sl[tid] = g_loss[tid];
    __syncthreads();
    for (int off = 64; off > 0; off >>= 1) {
        if (tid < off) sl[tid] += sl[tid + off];
        __syncthreads();
    }
    if (tid == 0) out[loss_idx] = sl[0] / (float)(Tt * Bb);
}

// ---------------------------------------------------------------------------
extern "C" void kernel_launch(void* const* d_in, const int* in_sizes, int n_in,
                              void* d_out, int out_size)
{
    const int*   tokens      = (const int*)  d_in[0];
    const int*   transitions = (const int*)  d_in[1];
    const float* embed_table = (const float*)d_in[2];
    const float* W_proj      = (const float*)d_in[3];
    const float* W_buf       = (const float*)d_in[4];
    const float* W_s1        = (const float*)d_in[5];
    const float* W_s2        = (const float*)d_in[6];
    const float* W_lat       = (const float*)d_in[7];
    const float* b_lat       = (const float*)d_in[8];
    const float* W_trans     = (const float*)d_in[9];
    const float* b_trans     = (const float*)d_in[10];
    const float* W_left      = (const float*)d_in[11];
    const float* W_right     = (const float*)d_in[12];
    const float* W_track     = (const float*)d_in[13];
    const float* b_reduce    = (const float*)d_in[14];
    float* out = (float*)d_out;

    embed_kernel<<<(Bb * Nn) / 16, 256>>>(tokens, embed_table, W_proj);
    spinn_seq<<<NGRP, 256>>>(transitions,
                             W_buf, W_s1, W_s2, W_lat, b_lat,
                             W_trans, b_trans,
                             W_left, W_right, W_track, b_reduce,
                             out);
    loss_kernel<<<1, 128>>>(out, out_size - 1);
}

// round 4
// speedup vs baseline: 1.8552x; 1.4613x over previous
#include <cuda_runtime.h>
#include <math.h>

#define Bb 128
#define Nn 128
#define Ee 300
#define Tt 255
#define CSZ 8                       // cluster size (CTAs per cluster)
#define GPB 8                       // batch elements per cluster

__device__ float g_buffer[Bb * Nn * 256];   // embedded+projected tokens
__device__ float g_stack [Bb * Nn * 256];   // per-batch stacks
__device__ float g_h     [Bb * 128];        // tracker h exchange
__device__ float g_loss  [Bb];

__device__ __forceinline__ float sigf(float x) { return 1.0f / (1.0f + expf(-x)); }

#define CLUSTER_SYNC() do { \
    asm volatile("barrier.cluster.arrive.aligned;" ::: "memory"); \
    asm volatile("barrier.cluster.wait.aligned;"   ::: "memory"); \
} while (0)

// ---------------------------------------------------------------------------
// Kernel 1: buffer[b,n,:] = embed_table[tokens[b,n]] @ W_proj
// ---------------------------------------------------------------------------
__global__ void __launch_bounds__(256) embed_kernel(
    const int*   __restrict__ tokens,
    const float* __restrict__ embed_table,
    const float* __restrict__ W_proj)
{
    __shared__ float se[16 * Ee];
    __shared__ int   stok[16];
    const int blk = blockIdx.x;
    const int tid = threadIdx.x;

    if (tid < 16) stok[tid] = tokens[blk * 16 + tid];
    __syncthreads();
    for (int idx = tid; idx < 16 * Ee; idx += 256) {
        int j = idx / Ee, e = idx - j * Ee;
        se[idx] = embed_table[(size_t)stok[j] * Ee + e];
    }
    __syncthreads();

    const int col = tid;
    float acc[16];
#pragma unroll
    for (int j = 0; j < 16; j++) acc[j] = 0.0f;
    for (int e = 0; e < Ee; e++) {
        float w = W_proj[e * 256 + col];
#pragma unroll
        for (int j = 0; j < 16; j++) acc[j] += se[j * Ee + e] * w;
    }
#pragma unroll
    for (int j = 0; j < 16; j++)
        g_buffer[(size_t)(blk * 16 + j) * 256 + col] = acc[j];
}

// ---------------------------------------------------------------------------
// Kernel 2: clustered scan. 16 clusters x 8 CTAs. Cluster owns 8 batches.
// CTA rank r owns tracker cols {g*128 + r*16 + jj} (g<4, jj<16) and
// tree cols {g*128 + r*16 + jj} (g<5), so h/c dims [r*16, r*16+16) are local.
// ---------------------------------------------------------------------------
struct Smem {
    float wK[512][64];          // tracker weight slice, [k][c_local]
    float bt[GPB][256];
    float s1v[GPB][256];
    float s2v[GPB][256];
    float h_s[GPB][128];
    float part[4 * 64 * 8];     // GEMM partials (tracker 4*512, tree 3*640)
    float lstm_loc[64][8];
    float gg_loc[80][8];
    float c_s[GPB][16];
    float bias_lat[64];
    float bias_red[80];
    float wtrans[256];
    float btr[2];
    int   str[GPB][Tt];
};

__global__ void __launch_bounds__(256, 1) __cluster_dims__(CSZ, 1, 1)
spinn_seq(
    const int*   __restrict__ transitions,
    const float* __restrict__ W_buf,  const float* __restrict__ W_s1,
    const float* __restrict__ W_s2,   const float* __restrict__ W_lat,
    const float* __restrict__ b_lat,
    const float* __restrict__ W_trans,const float* __restrict__ b_trans,
    const float* __restrict__ W_left, const float* __restrict__ W_right,
    const float* __restrict__ W_track,const float* __restrict__ b_reduce,
    float* __restrict__ out_final)
{
    extern __shared__ char smraw[];
    Smem* sm = (Smem*)smraw;

    const int tid  = threadIdx.x;
    const int r    = blockIdx.x & (CSZ - 1);     // cluster rank
    const int b0   = blockIdx.x & ~(CSZ - 1);    // first batch of cluster

    float*       stck = g_stack  + (size_t)b0 * Nn * 256;
    const float* buf  = g_buffer + (size_t)b0 * Nn * 256;

    // ---------------- init: weight slice, biases, transitions ----------------
    for (int idx = tid; idx < 512 * 64; idx += 256) {
        const int k = idx >> 6, c = idx & 63;
        const int G = ((c >> 4) << 7) + (r << 4) + (c & 15);
        float w;
        if      (k < 128) w = W_buf[k * 512 + G];
        else if (k < 256) w = W_s1 [(k - 128) * 512 + G];
        else if (k < 384) w = W_s2 [(k - 256) * 512 + G];
        else              w = W_lat[(k - 384) * 512 + G];
        sm->wK[k][c] = w;
    }
    if (tid < 64)  sm->bias_lat[tid] = b_lat[((tid >> 4) << 7) + (r << 4) + (tid & 15)];
    if (tid < 80)  sm->bias_red[tid] = b_reduce[((tid >> 4) << 7) + (r << 4) + (tid & 15)];
    if (tid < 256) sm->wtrans[tid] = W_trans[tid];
    if (tid < 2)   sm->btr[tid] = b_trans[tid];
    for (int i = tid; i < GPB * Tt; i += 256) {
        int g = i / Tt, t = i - g * Tt;
        sm->str[g][t] = transitions[(b0 + g) * Tt + t];
    }
    for (int i = tid; i < GPB * 128; i += 256) sm->h_s[i >> 7][i & 127] = 0.0f;
    for (int i = tid; i < GPB * 16;  i += 256) sm->c_s[i >> 4][i & 15]  = 0.0f;

    int ptr8[GPB], bptr8[GPB];
#pragma unroll
    for (int g = 0; g < GPB; g++) { ptr8[g] = 0; bptr8[g] = 0; }
    float loss_reg = 0.0f;
    float* pt = sm->part;

    __syncthreads();
    CLUSTER_SYNC();

    for (int t = 0; t < Tt; t++) {
        int tr[GPB];
        int orr = 0;
#pragma unroll
        for (int g = 0; g < GPB; g++) { tr[g] = sm->str[g][t]; orr |= tr[g]; }
        const bool any_red = (orr != 0);

        // -------- gather bt / s1 / s2 (float4; stack via L2) --------
        for (int i = tid; i < GPB * 64; i += 256) {
            const int b = i >> 6, q = (i & 63) * 4;
            const int btop = (bptr8[b] < Nn - 1) ? bptr8[b] : (Nn - 1);
            const int i1 = (ptr8[b] - 1 >= 0) ? ptr8[b] - 1 : 0;
            const int i2 = (ptr8[b] - 2 >= 0) ? ptr8[b] - 2 : 0;
            const float4 z = make_float4(0.f, 0.f, 0.f, 0.f);
            *(float4*)&sm->bt[b][q] = *(const float4*)&buf[((size_t)b * Nn + btop) * 256 + q];
            *(float4*)&sm->s1v[b][q] = (ptr8[b] >= 1) ?
                __ldcg((const float4*)&stck[((size_t)b * Nn + i1) * 256 + q]) : z;
            *(float4*)&sm->s2v[b][q] = (ptr8[b] >= 2) ?
                __ldcg((const float4*)&stck[((size_t)b * Nn + i2) * 256 + q]) : z;
        }
        __syncthreads();

        // -------- tracker GEMM: 64 cols x 8 batches, k split 4 ways --------
        {
            const int col = tid & 63, kc = tid >> 6;
            const float* xbase = (kc == 0) ? &sm->bt[0][0] :
                                 (kc == 1) ? &sm->s1v[0][0] :
                                 (kc == 2) ? &sm->s2v[0][0] : &sm->h_s[0][0];
            const int xs = (kc == 3) ? 128 : 256;
            const float* wrow = &sm->wK[kc * 128][col];
            float acc[GPB];
#pragma unroll
            for (int b = 0; b < GPB; b++) acc[b] = 0.0f;
            for (int kl = 0; kl < 128; kl += 4) {
                const float w0 = wrow[(kl + 0) * 64];
                const float w1 = wrow[(kl + 1) * 64];
                const float w2 = wrow[(kl + 2) * 64];
                const float w3 = wrow[(kl + 3) * 64];
#pragma unroll
                for (int b = 0; b < GPB; b++) {
                    const float4 x = *(const float4*)&xbase[b * xs + kl];
                    acc[b] += x.x * w0 + x.y * w1 + x.z * w2 + x.w * w3;
                }
            }
#pragma unroll
            for (int b = 0; b < GPB; b++) pt[kc * 512 + col * 8 + b] = acc[b];
        }
        __syncthreads();
        for (int idx = tid; idx < 512; idx += 256) {
            const int c = idx >> 3, b = idx & 7;
            float v = pt[c * 8 + b] + pt[512 + c * 8 + b]
                    + pt[1024 + c * 8 + b] + pt[1536 + c * 8 + b];
            if (t > 0) v += sm->bias_lat[c];
            sm->lstm_loc[c][b] = v;
        }
        __syncthreads();

        // -------- cell update for local dims, publish h --------
        if (tid < 128) {
            const int jj = tid >> 3, b = tid & 7;
            const float a = sm->lstm_loc[jj][b],      ii = sm->lstm_loc[16 + jj][b];
            const float f = sm->lstm_loc[32 + jj][b], o  = sm->lstm_loc[48 + jj][b];
            const float cn = sigf(f) * sm->c_s[b][jj] + sigf(ii) * tanhf(a);
            const float hn = sigf(o) * tanhf(cn);
            sm->c_s[b][jj] = cn;
            __stcg(&g_h[(b0 + b) * 128 + (r << 4) + jj], hn);
        }
        CLUSTER_SYNC();

        // -------- refresh full h --------
        {
            const int b = tid >> 5, q = (tid & 31) * 4;
            *(float4*)&sm->h_s[b][q] = __ldcg((const float4*)&g_h[(b0 + b) * 128 + q]);
        }
        __syncthreads();

        // -------- loss for this CTA's batch (rank r) --------
        if (tid < 32) {
            float p0 = 0.f, p1 = 0.f;
#pragma unroll
            for (int m = 0; m < 4; m++) {
                const int j = tid + 32 * m;
                const float h = sm->h_s[r][j];
                p0 += h * sm->wtrans[2 * j];
                p1 += h * sm->wtrans[2 * j + 1];
            }
#pragma unroll
            for (int off = 16; off > 0; off >>= 1) {
                p0 += __shfl_xor_sync(0xffffffffu, p0, off);
                p1 += __shfl_xor_sync(0xffffffffu, p1, off);
            }
            if (tid == 0) {
                const float l0 = p0 + sm->btr[0], l1 = p1 + sm->btr[1];
                const float m  = fmaxf(l0, l1);
                const float lse = m + logf(expf(l0 - m) + expf(l1 - m));
                loss_reg += lse - ((tr[r] == 0) ? l0 : l1);
            }
        }

        // -------- tree GEMM (skip if all 8 batches shift) --------
        if (any_red) {
            if (tid < 240) {
                const int kc = tid / 80, c = tid - kc * 80;
                const int Gt = ((c >> 4) << 7) + (r << 4) + (c & 15);
                const float* xbase = (kc == 0) ? &sm->s2v[0][0] :   // left  = s2
                                     (kc == 1) ? &sm->s1v[0][0] :   // right = s1
                                                 &sm->h_s[0][0];
                const int xs = (kc == 2) ? 128 : 256;
                const float* wb = (kc == 0) ? W_left : (kc == 1) ? W_right : W_track;
                float acc[GPB];
#pragma unroll
                for (int b = 0; b < GPB; b++) acc[b] = 0.0f;
#pragma unroll 2
                for (int kl = 0; kl < 128; kl += 4) {
                    const float w0 = __ldg(&wb[(kl + 0) * 640 + Gt]);
                    const float w1 = __ldg(&wb[(kl + 1) * 640 + Gt]);
                    const float w2 = __ldg(&wb[(kl + 2) * 640 + Gt]);
                    const float w3 = __ldg(&wb[(kl + 3) * 640 + Gt]);
#pragma unroll
                    for (int b = 0; b < GPB; b++) {
                        const float4 x = *(const float4*)&xbase[b * xs + kl];
                        acc[b] += x.x * w0 + x.y * w1 + x.z * w2 + x.w * w3;
                    }
                }
#pragma unroll
                for (int b = 0; b < GPB; b++) pt[kc * 640 + c * 8 + b] = acc[b];
            }
            __syncthreads();
            for (int idx = tid; idx < 640; idx += 256) {
                const int c = idx >> 3, b = idx & 7;
                sm->gg_loc[c][b] = pt[c * 8 + b] + pt[640 + c * 8 + b]
                                 + pt[1280 + c * 8 + b] + sm->bias_red[c];
            }
            __syncthreads();
        }

        // -------- compose + stack write (this CTA's 16 dims) --------
        if (tid < 128) {
            const int jj = tid >> 3, b = tid & 7;
            const int j = (r << 4) + jj;
            const bool sh = (tr[b] == 0);
            int wp = sh ? ptr8[b] : ((ptr8[b] - 2 >= 0) ? ptr8[b] - 2 : 0);
            if (wp < 0) wp = 0;
            if (wp > Nn - 1) wp = Nn - 1;
            float v0, v1;
            if (sh) {
                v0 = sm->bt[b][j]; v1 = sm->bt[b][128 + j];
            } else {
                const float a2 = sm->gg_loc[jj][b],      i2 = sm->gg_loc[16 + jj][b];
                const float f1 = sm->gg_loc[32 + jj][b], f2 = sm->gg_loc[48 + jj][b];
                const float o2 = sm->gg_loc[64 + jj][b];
                const float cn = tanhf(a2) * sigf(i2)
                               + sigf(f1) * sm->s2v[b][128 + j]   // left c
                               + sigf(f2) * sm->s1v[b][128 + j];  // right c
                v1 = cn; v0 = sigf(o2) * tanhf(cn);
            }
            __stcg(&stck[((size_t)b * Nn + wp) * 256 + j],       v0);
            __stcg(&stck[((size_t)b * Nn + wp) * 256 + 128 + j], v1);
        }
#pragma unroll
        for (int g = 0; g < GPB; g++) {
            const bool sh = (tr[g] == 0);
            ptr8[g]  += sh ? 1 : -1;
            bptr8[g] += sh ? 1 : 0;
        }
        CLUSTER_SYNC();   // stack + ordering for next gather
    }

    // -------- final output: CTA rank r copies batch b0+r's stack top --------
    if (tid < 64) {
        int fin = (ptr8[r] - 1 >= 0) ? ptr8[r] - 1 : 0;
        if (fin > Nn - 1) fin = Nn - 1;
        const float4 v = __ldcg((const float4*)&stck[((size_t)r * Nn + fin) * 256 + tid * 4]);
        *(float4*)&out_final[(size_t)(b0 + r) * 256 + tid * 4] = v;
    }
    if (tid == 0) g_loss[b0 + r] = loss_reg;
}

// ---------------------------------------------------------------------------
// Kernel 3: loss reduction
// ---------------------------------------------------------------------------
__global__ void loss_kernel(float* __restrict__ out, int loss_idx)
{
    __shared__ float sl[128];
    int tid = threadIdx.x;
    sl[tid] = g_loss[tid];
    __syncthreads();
    for (int off = 64; off > 0; off >>= 1) {
        if (tid < off) sl[tid] += sl[tid + off];
        __syncthreads();
    }
    if (tid == 0) out[loss_idx] = sl[0] / (float)(Tt * Bb);
}

// ---------------------------------------------------------------------------
extern "C" void kernel_launch(void* const* d_in, const int* in_sizes, int n_in,
                              void* d_out, int out_size)
{
    const int*   tokens      = (const int*)  d_in[0];
    const int*   transitions = (const int*)  d_in[1];
    const float* embed_table = (const float*)d_in[2];
    const float* W_proj      = (const float*)d_in[3];
    const float* W_buf       = (const float*)d_in[4];
    const float* W_s1        = (const float*)d_in[5];
    const float* W_s2        = (const float*)d_in[6];
    const float* W_lat       = (const float*)d_in[7];
    const float* b_lat       = (const float*)d_in[8];
    const float* W_trans     = (const float*)d_in[9];
    const float* b_trans     = (const float*)d_in[10];
    const float* W_left      = (const float*)d_in[11];
    const float* W_right     = (const float*)d_in[12];
    const float* W_track     = (const float*)d_in[13];
    const float* b_reduce    = (const float*)d_in[14];
    float* out = (float*)d_out;

    static bool attr_done = false;
    if (!attr_done) {
        cudaFuncSetAttribute(spinn_seq,
                             cudaFuncAttributeMaxDynamicSharedMemorySize,
                             (int)sizeof(Smem));
        attr_done = true;
    }

    embed_kernel<<<(Bb * Nn) / 16, 256>>>(tokens, embed_table, W_proj);
    spinn_seq<<<Bb, 256, sizeof(Smem)>>>(transitions,
                                         W_buf, W_s1, W_s2, W_lat, b_lat,
                                         W_trans, b_trans,
                                         W_left, W_right, W_track, b_reduce,
                                         out);
    loss_kernel<<<1, 128>>>(out, out_size - 1);
}

// round 5
// speedup vs baseline: 2.1742x; 1.1719x over previous
#include <cuda_runtime.h>
#include <cuda_bf16.h>
#include <math.h>

#define Bb 128
#define Nn 128
#define Ee 300
#define Tt 255
#define CSZ 8
#define GPB 8

__device__ float g_buffer[Bb * Nn * 256];
__device__ float g_stack [Bb * Nn * 256];
__device__ float g_loss  [Bb];

__device__ __forceinline__ float sigf(float x) { return 1.0f / (1.0f + expf(-x)); }

__device__ __forceinline__ unsigned smem_u32(const void* p) {
    unsigned a;
    asm("{ .reg .u64 t; cvta.to.shared.u64 t, %1; cvt.u32.u64 %0, t; }" : "=r"(a) : "l"(p));
    return a;
}
__device__ __forceinline__ void fence_cluster() {
    asm volatile("fence.acq_rel.cluster;" ::: "memory");
}
__device__ __forceinline__ void arrive_peer(unsigned la, int p) {
    asm volatile("{ .reg .b32 ra; mapa.shared::cluster.u32 ra, %0, %1;"
                 " mbarrier.arrive.shared::cluster.b64 _, [ra]; }"
                 :: "r"(la), "r"(p) : "memory");
}
__device__ __forceinline__ void wait_parity_cluster(unsigned a, unsigned par) {
    asm volatile("{ .reg .pred P;\n"
                 "W_%=:\n"
                 " mbarrier.try_wait.parity.acquire.cluster.shared::cta.b64 P, [%0], %1, 0x989680;\n"
                 " @P bra D_%=;\n"
                 " bra W_%=;\n"
                 "D_%=:\n}"
                 :: "r"(a), "r"(par) : "memory");
}
__device__ __forceinline__ void st_remote_f32(unsigned la, int p, float v) {
    asm volatile("{ .reg .b32 ra; mapa.shared::cluster.u32 ra, %0, %1;"
                 " st.shared::cluster.f32 [ra], %2; }"
                 :: "r"(la), "r"(p), "f"(v) : "memory");
}

// ---------------------------------------------------------------------------
// Kernel 1: buffer[b,n,:] = embed_table[tokens[b,n]] @ W_proj
// ---------------------------------------------------------------------------
__global__ void __launch_bounds__(256) embed_kernel(
    const int*   __restrict__ tokens,
    const float* __restrict__ embed_table,
    const float* __restrict__ W_proj)
{
    __shared__ float se[16 * Ee];
    __shared__ int   stok[16];
    const int blk = blockIdx.x;
    const int tid = threadIdx.x;

    if (tid < 16) stok[tid] = tokens[blk * 16 + tid];
    __syncthreads();
    for (int idx = tid; idx < 16 * Ee; idx += 256) {
        int j = idx / Ee, e = idx - j * Ee;
        se[idx] = embed_table[(size_t)stok[j] * Ee + e];
    }
    __syncthreads();

    const int col = tid;
    float acc[16];
#pragma unroll
    for (int j = 0; j < 16; j++) acc[j] = 0.0f;
    for (int e = 0; e < Ee; e++) {
        float w = W_proj[e * 256 + col];
#pragma unroll
        for (int j = 0; j < 16; j++) acc[j] += se[j * Ee + e] * w;
    }
#pragma unroll
    for (int j = 0; j < 16; j++)
        g_buffer[(size_t)(blk * 16 + j) * 256 + col] = acc[j];
}

// ---------------------------------------------------------------------------
// Kernel 2: clustered scan, all weights SMEM-resident, mbarrier cluster sync
// ---------------------------------------------------------------------------
struct __align__(16) Smem {
    float wK[384 * 64];             // W_buf/W_s1/W_s2 slice fp32
    float h_s[2][GPB][128];         // double-buffered tracker h
    float bt[GPB][256];
    float s1v[GPB][256];
    float s2v[GPB][256];
    float pt[2048];                 // GEMM partials
    float c_s[GPB][16];
    float bias_lat[64];
    float bias_red[80];
    float wtrans[256];
    float btr[2];
    int   sptr[GPB], sbptr[GPB], swp[GPB];
    unsigned long long mbar[2];     // [0]=h_bar, [1]=stack_bar
    __nv_bfloat16 wLat[64 * 130];   // W_lat slice bf16, [c][k] pad 130
    __nv_bfloat16 wT[80 * 390];     // tree slice bf16, [c][k] pad 390
    unsigned trbits[GPB][8];
};

__global__ void __launch_bounds__(256, 1) __cluster_dims__(CSZ, 1, 1)
spinn_seq(
    const int*   __restrict__ transitions,
    const float* __restrict__ W_buf,  const float* __restrict__ W_s1,
    const float* __restrict__ W_s2,   const float* __restrict__ W_lat,
    const float* __restrict__ b_lat,
    const float* __restrict__ W_trans,const float* __restrict__ b_trans,
    const float* __restrict__ W_left, const float* __restrict__ W_right,
    const float* __restrict__ W_track,const float* __restrict__ b_reduce,
    float* __restrict__ out_final)
{
    extern __shared__ char smraw[];
    Smem* sm = (Smem*)smraw;
    const int tid = threadIdx.x;
    const int r   = blockIdx.x & (CSZ - 1);
    const int b0  = blockIdx.x & ~(CSZ - 1);

    float*       stck = g_stack  + (size_t)b0 * Nn * 256;
    const float* buf  = g_buffer + (size_t)b0 * Nn * 256;

    // -------------------- init --------------------
    for (int idx = tid; idx < 384 * 64; idx += 256) {
        int k = idx >> 6, c = idx & 63;
        int G = ((c >> 4) << 7) + (r << 4) + (c & 15);
        float w = (k < 128) ? W_buf[k * 512 + G]
                : (k < 256) ? W_s1[(k - 128) * 512 + G]
                            : W_s2[(k - 256) * 512 + G];
        sm->wK[idx] = w;
    }
    for (int idx = tid; idx < 64 * 128; idx += 256) {
        int c = idx >> 7, k = idx & 127;
        int G = ((c >> 4) << 7) + (r << 4) + (c & 15);
        sm->wLat[c * 130 + k] = __float2bfloat16(W_lat[k * 512 + G]);
    }
    for (int idx = tid; idx < 80 * 384; idx += 256) {
        int c = idx / 384, k = idx - c * 384;
        int G = ((c >> 4) << 7) + (r << 4) + (c & 15);
        float w = (k < 128) ? W_left[k * 640 + G]
                : (k < 256) ? W_right[(k - 128) * 640 + G]
                            : W_track[(k - 256) * 640 + G];
        sm->wT[c * 390 + k] = __float2bfloat16(w);
    }
    if (tid < 64) sm->bias_lat[tid] = b_lat[((tid >> 4) << 7) + (r << 4) + (tid & 15)];
    if (tid < 80) sm->bias_red[tid] = b_reduce[((tid >> 4) << 7) + (r << 4) + (tid & 15)];
    sm->wtrans[tid] = W_trans[tid];
    if (tid < 2) sm->btr[tid] = b_trans[tid];
    if (tid < 64) {
        int g = tid >> 3, w = tid & 7;
        unsigned bits = 0;
        for (int i = 0; i < 32; i++) {
            int tt = w * 32 + i;
            if (tt < Tt) bits |= (unsigned)(transitions[(b0 + g) * Tt + tt] & 1) << i;
        }
        sm->trbits[g][w] = bits;
    }
    for (int i = tid; i < GPB * 128; i += 256) ((float*)sm->h_s)[i] = 0.f;  // h_s[0]
    for (int i = tid; i < GPB * 16;  i += 256) ((float*)sm->c_s)[i] = 0.f;
    if (tid < GPB) { sm->sptr[tid] = 0; sm->sbptr[tid] = 0; }
    if (tid == 0) {
        unsigned mb = smem_u32(&sm->mbar[0]);
        asm volatile("mbarrier.init.shared.b64 [%0], %1;" :: "r"(mb),   "r"(CSZ) : "memory");
        asm volatile("mbarrier.init.shared.b64 [%0], %1;" :: "r"(mb+8), "r"(CSZ) : "memory");
    }
    __syncthreads();
    asm volatile("barrier.cluster.arrive.aligned;" ::: "memory");
    asm volatile("barrier.cluster.wait.aligned;"   ::: "memory");

    const unsigned hbar   = smem_u32(&sm->mbar[0]);
    const unsigned sbar   = hbar + 8;
    const unsigned hsbase = smem_u32(&sm->h_s[0][0][0]);

    float loss_reg = 0.f;

    for (int t = 0; t < Tt; t++) {
        const int word = t >> 5, bit = t & 31;
        if (t > 0) wait_parity_cluster(sbar, (t - 1) & 1);

        int pv[GPB], bv[GPB];
#pragma unroll
        for (int g = 0; g < GPB; g++) { pv[g] = sm->sptr[g]; bv[g] = sm->sbptr[g]; }
        unsigned anyr = 0;
#pragma unroll
        for (int g = 0; g < GPB; g++) anyr |= (sm->trbits[g][word] >> bit) & 1u;
        const bool any_red = (anyr != 0);

        if (tid == 0) {
#pragma unroll
            for (int g = 0; g < GPB; g++) {
                int trg = (sm->trbits[g][word] >> bit) & 1;
                int p = pv[g];
                int wp = trg ? ((p - 2 >= 0) ? p - 2 : 0) : p;
                if (wp > Nn - 1) wp = Nn - 1;
                sm->swp[g] = wp;
            }
        }

        // -------- gather (b static -> no spills; 8-deep MLP) --------
        {
            const int sel = tid >> 6, q = (tid & 63) * 4;
            const float4 z = make_float4(0.f, 0.f, 0.f, 0.f);
#pragma unroll
            for (int b = 0; b < GPB; b++) {
                if (sel == 0) {
                    int btop = (bv[b] < Nn - 1) ? bv[b] : (Nn - 1);
                    *(float4*)&sm->bt[b][q] =
                        *(const float4*)&buf[((size_t)b * Nn + btop) * 256 + q];
                } else if (sel == 1) {
                    int i1 = (pv[b] - 1 >= 0) ? pv[b] - 1 : 0;
                    *(float4*)&sm->s1v[b][q] = (pv[b] >= 1) ?
                        __ldcg((const float4*)&stck[((size_t)b * Nn + i1) * 256 + q]) : z;
                } else if (sel == 2) {
                    int i2 = (pv[b] - 2 >= 0) ? pv[b] - 2 : 0;
                    *(float4*)&sm->s2v[b][q] = (pv[b] >= 2) ?
                        __ldcg((const float4*)&stck[((size_t)b * Nn + i2) * 256 + q]) : z;
                }
            }
        }
        __syncthreads();

        const int rb = t & 1, wb = 1 - rb;

        // -------- tracker GEMM --------
        {
            const int col = tid & 63, kc = tid >> 6;
            float acc[GPB];
#pragma unroll
            for (int b = 0; b < GPB; b++) acc[b] = 0.f;
            if (kc < 3) {
                const float* xb = (kc == 0) ? &sm->bt[0][0]
                                : (kc == 1) ? &sm->s1v[0][0] : &sm->s2v[0][0];
                const float* wr = &sm->wK[kc * 128 * 64 + col];
                for (int kl = 0; kl < 128; kl += 4) {
                    float w0 = wr[(kl + 0) * 64], w1 = wr[(kl + 1) * 64];
                    float w2 = wr[(kl + 2) * 64], w3 = wr[(kl + 3) * 64];
#pragma unroll
                    for (int b = 0; b < GPB; b++) {
                        float4 x = *(const float4*)&xb[b * 256 + kl];
                        acc[b] += x.x * w0 + x.y * w1 + x.z * w2 + x.w * w3;
                    }
                }
            } else {
                const float* xb = &sm->h_s[rb][0][0];
                const __nv_bfloat16* wl = &sm->wLat[col * 130];
                for (int kl = 0; kl < 128; kl += 4) {
                    float2 wf0 = __bfloat1622float2(*(const __nv_bfloat162*)&wl[kl]);
                    float2 wf1 = __bfloat1622float2(*(const __nv_bfloat162*)&wl[kl + 2]);
#pragma unroll
                    for (int b = 0; b < GPB; b++) {
                        float4 x = *(const float4*)&xb[b * 128 + kl];
                        acc[b] += x.x * wf0.x + x.y * wf0.y + x.z * wf1.x + x.w * wf1.y;
                    }
                }
            }
            *(float4*)&sm->pt[kc * 512 + col * 8]     = make_float4(acc[0], acc[1], acc[2], acc[3]);
            *(float4*)&sm->pt[kc * 512 + col * 8 + 4] = make_float4(acc[4], acc[5], acc[6], acc[7]);
        }
        __syncthreads();

        // -------- cell update + DSMEM h publish --------
        if (tid < 128) {
            const int jj = tid >> 3, b = tid & 7;
            float ga[4];
#pragma unroll
            for (int g = 0; g < 4; g++) {
                int c = g * 16 + jj;
                float v = sm->pt[c * 8 + b] + sm->pt[512 + c * 8 + b]
                        + sm->pt[1024 + c * 8 + b] + sm->pt[1536 + c * 8 + b];
                if (t > 0) v += sm->bias_lat[c];
                ga[g] = v;
            }
            float cn = sigf(ga[2]) * sm->c_s[b][jj] + sigf(ga[1]) * tanhf(ga[0]);
            float hn = sigf(ga[3]) * tanhf(cn);
            sm->c_s[b][jj] = cn;
            unsigned la = hsbase + (unsigned)(((wb * GPB + b) * 128 + (r << 4) + jj) * 4);
#pragma unroll
            for (int p = 0; p < CSZ; p++) st_remote_f32(la, p, hn);
        }
        __syncthreads();
        if (tid < CSZ) { fence_cluster(); arrive_peer(hbar, tid); }
        wait_parity_cluster(hbar, t & 1);

        // -------- loss (new h, batch r) --------
        if (tid < 32) {
            float p0 = 0.f, p1 = 0.f;
#pragma unroll
            for (int m = 0; m < 4; m++) {
                int j = tid + 32 * m;
                float h = sm->h_s[wb][r][j];
                p0 += h * sm->wtrans[2 * j];
                p1 += h * sm->wtrans[2 * j + 1];
            }
#pragma unroll
            for (int off = 16; off > 0; off >>= 1) {
                p0 += __shfl_xor_sync(0xffffffffu, p0, off);
                p1 += __shfl_xor_sync(0xffffffffu, p1, off);
            }
            if (tid == 0) {
                float l0 = p0 + sm->btr[0], l1 = p1 + sm->btr[1];
                float m = fmaxf(l0, l1);
                float lse = m + logf(expf(l0 - m) + expf(l1 - m));
                int trr = (sm->trbits[r][word] >> bit) & 1;
                loss_reg += lse - ((trr == 0) ? l0 : l1);
            }
        }

        // -------- tree GEMM (SMEM bf16 weights) --------
        if (any_red) {
            if (tid < 240) {
                const int kc = tid / 80, c = tid - kc * 80;
                const float* xb = (kc == 0) ? &sm->s2v[0][0]
                                : (kc == 1) ? &sm->s1v[0][0] : &sm->h_s[wb][0][0];
                const int xs = (kc == 2) ? 128 : 256;
                const __nv_bfloat16* wr = &sm->wT[c * 390 + kc * 128];
                float acc[GPB];
#pragma unroll
                for (int b = 0; b < GPB; b++) acc[b] = 0.f;
                for (int kl = 0; kl < 128; kl += 4) {
                    float2 wf0 = __bfloat1622float2(*(const __nv_bfloat162*)&wr[kl]);
                    float2 wf1 = __bfloat1622float2(*(const __nv_bfloat162*)&wr[kl + 2]);
#pragma unroll
                    for (int b = 0; b < GPB; b++) {
                        float4 x = *(const float4*)&xb[b * xs + kl];
                        acc[b] += x.x * wf0.x + x.y * wf0.y + x.z * wf1.x + x.w * wf1.y;
                    }
                }
                *(float4*)&sm->pt[kc * 640 + c * 8]     = make_float4(acc[0], acc[1], acc[2], acc[3]);
                *(float4*)&sm->pt[kc * 640 + c * 8 + 4] = make_float4(acc[4], acc[5], acc[6], acc[7]);
            }
            __syncthreads();
        }

        // -------- compose + stack write --------
        if (tid < 128) {
            const int jj = tid >> 3, b = tid & 7;
            const int j = (r << 4) + jj;
            const int trb = (sm->trbits[b][word] >> bit) & 1;
            const int wp = sm->swp[b];
            float v0, v1;
            if (trb == 0) {
                v0 = sm->bt[b][j]; v1 = sm->bt[b][128 + j];
            } else {
                float gg[5];
#pragma unroll
                for (int g = 0; g < 5; g++) {
                    int c = g * 16 + jj;
                    gg[g] = sm->pt[c * 8 + b] + sm->pt[640 + c * 8 + b]
                          + sm->pt[1280 + c * 8 + b] + sm->bias_red[c];
                }
                float cn = tanhf(gg[0]) * sigf(gg[1])
                         + sigf(gg[2]) * sm->s2v[b][128 + j]     // left c
                         + sigf(gg[3]) * sm->s1v[b][128 + j];    // right c
                v1 = cn; v0 = sigf(gg[4]) * tanhf(cn);
            }
            __stcg(&stck[((size_t)b * Nn + wp) * 256 + j], v0);
            __stcg(&stck[((size_t)b * Nn + wp) * 256 + 128 + j], v1);
        }
        if (tid == 0) {
#pragma unroll
            for (int g = 0; g < GPB; g++) {
                int trg = (sm->trbits[g][word] >> bit) & 1;
                sm->sptr[g]  += trg ? -1 : 1;
                sm->sbptr[g] += trg ? 0 : 1;
            }
        }
        __syncthreads();
        if (tid < CSZ) { fence_cluster(); arrive_peer(sbar, tid); }
    }

    fence_cluster();
    asm volatile("barrier.cluster.arrive.aligned;" ::: "memory");
    asm volatile("barrier.cluster.wait.aligned;"   ::: "memory");

    if (tid < 64) {
        int pr = sm->sptr[r];
        int fin = (pr - 1 >= 0) ? pr - 1 : 0;
        if (fin > Nn - 1) fin = Nn - 1;
        float4 v = __ldcg((const float4*)&stck[((size_t)r * Nn + fin) * 256 + tid * 4]);
        *(float4*)&out_final[(size_t)(b0 + r) * 256 + tid * 4] = v;
    }
    if (tid == 0) g_loss[b0 + r] = loss_reg;
}

// ---------------------------------------------------------------------------
// Kernel 3: loss reduction
// ---------------------------------------------------------------------------
__global__ void loss_kernel(float* __restrict__ out, int loss_idx)
{
    __shared__ float sl[128];
    int tid = threadIdx.x;
    sl[tid] = g_loss[tid];
    __syncthreads();
    for (int off = 64; off > 0; off >>= 1) {
        if (tid < off) sl[tid] += sl[tid + off];
        __syncthreads();
    }
    if (tid == 0) out[loss_idx] = sl[0] / (float)(Tt * Bb);
}

// ---------------------------------------------------------------------------
extern "C" void kernel_launch(void* const* d_in, const int* in_sizes, int n_in,
                              void* d_out, int out_size)
{
    const int*   tokens      = (const int*)  d_in[0];
    const int*   transitions = (const int*)  d_in[1];
    const float* embed_table = (const float*)d_in[2];
    const float* W_proj      = (const float*)d_in[3];
    const float* W_buf       = (const float*)d_in[4];
    const float* W_s1        = (const float*)d_in[5];
    const float* W_s2        = (const float*)d_in[6];
    const float* W_lat       = (const float*)d_in[7];
    const float* b_lat       = (const float*)d_in[8];
    const float* W_trans     = (const float*)d_in[9];
    const float* b_trans     = (const float*)d_in[10];
    const float* W_left      = (const float*)d_in[11];
    const float* W_right     = (const float*)d_in[12];
    const float* W_track     = (const float*)d_in[13];
    const float* b_reduce    = (const float*)d_in[14];
    float* out = (float*)d_out;

    static bool attr_done = false;
    if (!attr_done) {
        cudaFuncSetAttribute(spinn_seq,
                             cudaFuncAttributeMaxDynamicSharedMemorySize,
                             (int)sizeof(Smem));
        attr_done = true;
    }

    embed_kernel<<<(Bb * Nn) / 16, 256>>>(tokens, embed_table, W_proj);
    spinn_seq<<<Bb, 256, sizeof(Smem)>>>(transitions,
                                         W_buf, W_s1, W_s2, W_lat, b_lat,
                                         W_trans, b_trans,
                                         W_left, W_right, W_track, b_reduce,
                                         out);
    loss_kernel<<<1, 128>>>(out, out_size - 1);
}

// round 6
// speedup vs baseline: 2.7087x; 1.2458x over previous
#include <cuda_runtime.h>
#include <cuda_fp16.h>
#include <math.h>

#define Bb 128
#define Nn 128
#define Ee 300
#define Tt 255
#define CSZ 8
#define GPB 8

__device__ float g_buffer[Bb * Nn * 256];
__device__ float g_stack [Bb * Nn * 256];
__device__ float g_loss  [Bb];

__device__ __forceinline__ float sigf(float x) { return 1.0f / (1.0f + expf(-x)); }

__device__ __forceinline__ unsigned smem_u32(const void* p) {
    unsigned a;
    asm("{ .reg .u64 t; cvta.to.shared.u64 t, %1; cvt.u32.u64 %0, t; }" : "=r"(a) : "l"(p));
    return a;
}
__device__ __forceinline__ void fence_cluster() {
    asm volatile("fence.acq_rel.cluster;" ::: "memory");
}
__device__ __forceinline__ void arrive_peer(unsigned la, int p) {
    asm volatile("{ .reg .b32 ra; mapa.shared::cluster.u32 ra, %0, %1;"
                 " mbarrier.arrive.shared::cluster.b64 _, [ra]; }"
                 :: "r"(la), "r"(p) : "memory");
}
__device__ __forceinline__ void wait_parity_cluster(unsigned a, unsigned par) {
    asm volatile("{ .reg .pred P;\n"
                 "W_%=:\n"
                 " mbarrier.try_wait.parity.acquire.cluster.shared::cta.b64 P, [%0], %1, 0x989680;\n"
                 " @P bra D_%=;\n"
                 " bra W_%=;\n"
                 "D_%=:\n}"
                 :: "r"(a), "r"(par) : "memory");
}
__device__ __forceinline__ void st_remote_f32(unsigned la, int p, float v) {
    asm volatile("{ .reg .b32 ra; mapa.shared::cluster.u32 ra, %0, %1;"
                 " st.shared::cluster.f32 [ra], %2; }"
                 :: "r"(la), "r"(p), "f"(v) : "memory");
}

// ---------------------------------------------------------------------------
// Kernel 1: buffer[b,n,:] = embed_table[tokens[b,n]] @ W_proj
// ---------------------------------------------------------------------------
__global__ void __launch_bounds__(256) embed_kernel(
    const int*   __restrict__ tokens,
    const float* __restrict__ embed_table,
    const float* __restrict__ W_proj)
{
    __shared__ float se[16 * Ee];
    __shared__ int   stok[16];
    const int blk = blockIdx.x;
    const int tid = threadIdx.x;

    if (tid < 16) stok[tid] = tokens[blk * 16 + tid];
    __syncthreads();
    for (int idx = tid; idx < 16 * Ee; idx += 256) {
        int j = idx / Ee, e = idx - j * Ee;
        se[idx] = embed_table[(size_t)stok[j] * Ee + e];
    }
    __syncthreads();

    const int col = tid;
    float acc[16];
#pragma unroll
    for (int j = 0; j < 16; j++) acc[j] = 0.0f;
    for (int e = 0; e < Ee; e++) {
        float w = W_proj[e * 256 + col];
#pragma unroll
        for (int j = 0; j < 16; j++) acc[j] += se[j * Ee + e] * w;
    }
#pragma unroll
    for (int j = 0; j < 16; j++)
        g_buffer[(size_t)(blk * 16 + j) * 256 + col] = acc[j];
}

// ---------------------------------------------------------------------------
// Kernel 2: clustered scan with rolling smem stack state.
// ---------------------------------------------------------------------------
struct __align__(16) Smem {
    float wK[2 * 128 * 64];         // W_buf, W_s1 fp32 [k][64]
    float h_s[2][GPB][128];
    float bt[GPB][256];
    float s1v[GPB][256];
    float s2v[GPB][256];
    float red_s[GPB][256];          // reduced [h|c] exchange
    float pt[2048];
    float c_s[GPB][16];
    float bias_lat[64];
    float bias_red[80];
    float wtrans[256];
    float btr[2];
    int   fin_ptr[GPB];
    unsigned long long mbar[2];     // [0]=hbar, [1]=sbar
    __half wS2[64 * 130];
    __half wLat[64 * 130];
    __half wT[80 * 386];            // [c][kc*128+k], pad 386
    unsigned trbits[GPB][8];
    unsigned char sch_wp[Tt][GPB];
    unsigned char sch_bt[Tt + 1][GPB];
    signed char   sch_rf[Tt][GPB];
};

__global__ void __launch_bounds__(256, 1) __cluster_dims__(CSZ, 1, 1)
spinn_seq(
    const int*   __restrict__ transitions,
    const float* __restrict__ W_buf,  const float* __restrict__ W_s1,
    const float* __restrict__ W_s2,   const float* __restrict__ W_lat,
    const float* __restrict__ b_lat,
    const float* __restrict__ W_trans,const float* __restrict__ b_trans,
    const float* __restrict__ W_left, const float* __restrict__ W_right,
    const float* __restrict__ W_track,const float* __restrict__ b_reduce,
    float* __restrict__ out_final)
{
    extern __shared__ char smraw[];
    Smem* sm = (Smem*)smraw;
    const int tid = threadIdx.x;
    const int r   = blockIdx.x & (CSZ - 1);
    const int b0  = blockIdx.x & ~(CSZ - 1);

    float*       stck = g_stack  + (size_t)b0 * Nn * 256;
    const float* buf  = g_buffer + (size_t)b0 * Nn * 256;

    // ---------------- init ----------------
    for (int idx = tid; idx < 2 * 128 * 64; idx += 256) {
        int k = idx >> 6, c = idx & 63;
        int G = ((c >> 4) << 7) + (r << 4) + (c & 15);
        sm->wK[idx] = (k < 128) ? W_buf[k * 512 + G] : W_s1[(k - 128) * 512 + G];
    }
    for (int idx = tid; idx < 64 * 128; idx += 256) {
        int c = idx >> 7, k = idx & 127;
        int G = ((c >> 4) << 7) + (r << 4) + (c & 15);
        sm->wS2 [c * 130 + k] = __float2half(W_s2 [k * 512 + G]);
        sm->wLat[c * 130 + k] = __float2half(W_lat[k * 512 + G]);
    }
    for (int idx = tid; idx < 80 * 384; idx += 256) {
        int c = idx / 384, k = idx - c * 384;
        int G = ((c >> 4) << 7) + (r << 4) + (c & 15);
        float w = (k < 128) ? W_left[k * 640 + G]
                : (k < 256) ? W_right[(k - 128) * 640 + G]
                            : W_track[(k - 256) * 640 + G];
        sm->wT[c * 386 + k] = __float2half(w);
    }
    if (tid < 64) sm->bias_lat[tid] = b_lat[((tid >> 4) << 7) + (r << 4) + (tid & 15)];
    if (tid < 80) sm->bias_red[tid] = b_reduce[((tid >> 4) << 7) + (r << 4) + (tid & 15)];
    sm->wtrans[tid] = W_trans[tid];
    if (tid < 2) sm->btr[tid] = b_trans[tid];
    if (tid < 64) {
        int g = tid >> 3, w = tid & 7;
        unsigned bits = 0;
        for (int i = 0; i < 32; i++) {
            int tt = w * 32 + i;
            if (tt < Tt) bits |= (unsigned)(transitions[(b0 + g) * Tt + tt] & 1) << i;
        }
        sm->trbits[g][w] = bits;
    }
    for (int i = tid; i < 2 * GPB * 128; i += 256) ((float*)sm->h_s)[i] = 0.f;
    for (int i = tid; i < GPB * 16;  i += 256) ((float*)sm->c_s)[i] = 0.f;
    for (int i = tid; i < GPB * 256; i += 256) {
        ((float*)sm->s1v)[i] = 0.f;
        ((float*)sm->s2v)[i] = 0.f;
        ((float*)sm->red_s)[i] = 0.f;
    }
    // initial bt = buffer row 0
    for (int i = tid; i < GPB * 64; i += 256) {
        int b = i >> 6, q = (i & 63) * 4;
        *(float4*)&sm->bt[b][q] = *(const float4*)&buf[((size_t)b * Nn) * 256 + q];
    }
    if (tid == 0) {
        unsigned mb = smem_u32(&sm->mbar[0]);
        asm volatile("mbarrier.init.shared.b64 [%0], %1;" :: "r"(mb),   "r"(CSZ) : "memory");
        asm volatile("mbarrier.init.shared.b64 [%0], %1;" :: "r"(mb+8), "r"(CSZ) : "memory");
    }
    __syncthreads();

    // ---- precompute per-batch schedules (ptr/bptr fully static) ----
    if (tid < GPB) {
        const int g = tid;
        int p = 0, bp = 0;
        for (int t = 0; t < Tt; t++) {
            int trv = (sm->trbits[g][t >> 5] >> (t & 31)) & 1;
            int bi = (bp < Nn - 1) ? bp : (Nn - 1);
            sm->sch_bt[t][g] = (unsigned char)bi;
            int wp = trv ? ((p - 2 >= 0) ? p - 2 : 0) : p;
            if (wp > Nn - 1) wp = Nn - 1;
            sm->sch_wp[t][g] = (unsigned char)wp;
            sm->sch_rf[t][g] = (signed char)((trv && p >= 3) ? (p - 3) : -1);
            p  += trv ? -1 : 1;
            bp += trv ? 0 : 1;
        }
        sm->sch_bt[Tt][g] = sm->sch_bt[Tt - 1][g];
        int fin = (p - 1 >= 0) ? p - 1 : 0;
        sm->fin_ptr[g] = (fin > Nn - 1) ? Nn - 1 : fin;
    }
    __syncthreads();
    asm volatile("barrier.cluster.arrive.aligned;" ::: "memory");
    asm volatile("barrier.cluster.wait.aligned;"   ::: "memory");

    const unsigned hbar    = smem_u32(&sm->mbar[0]);
    const unsigned sbar    = hbar + 8;
    const unsigned hsbase  = smem_u32(&sm->h_s[0][0][0]);
    const unsigned redbase = smem_u32(&sm->red_s[0][0]);

    const int pb = tid >> 5;             // prefetch/rename batch
    const int pd = (tid & 31) * 8;       // dim base (8 floats)
    const float4 z4 = make_float4(0.f, 0.f, 0.f, 0.f);
    float4 rfa = z4, rfb = z4;           // refill regs (consumed next step)
    float4 bna = z4, bnb = z4;           // next-bt regs (consumed end of step)
    float loss_reg = 0.f;

    for (int t = 0; t < Tt; t++) {
        const int w5 = t >> 5, b5 = t & 31;
        const int rb = t & 1, wbuf = 1 - rb;

        if (t > 0) {
            wait_parity_cluster(sbar, (t - 1) & 1);
            // deferred reduce-rename: s1 <- reduced (red_s), s2 <- refill regs
            if ((sm->trbits[pb][(t - 1) >> 5] >> ((t - 1) & 31)) & 1) {
                float4 r0 = *(const float4*)&sm->red_s[pb][pd];
                float4 r1 = *(const float4*)&sm->red_s[pb][pd + 4];
                *(float4*)&sm->s1v[pb][pd]     = r0;
                *(float4*)&sm->s1v[pb][pd + 4] = r1;
                *(float4*)&sm->s2v[pb][pd]     = rfa;
                *(float4*)&sm->s2v[pb][pd + 4] = rfb;
            }
        }
        // prefetches for this step's tail / next step's head
        {
            int nbt = sm->sch_bt[t + 1][pb];
            const float* bsrc = &buf[((size_t)pb * Nn + nbt) * 256 + pd];
            bna = __ldg((const float4*)bsrc);
            bnb = __ldg((const float4*)(bsrc + 4));
            int rfi = sm->sch_rf[t][pb];
            if (rfi >= 0) {
                const float* rsrc = &stck[((size_t)pb * Nn + rfi) * 256 + pd];
                rfa = __ldcg((const float4*)rsrc);
                rfb = __ldcg((const float4*)(rsrc + 4));
            } else { rfa = z4; rfb = z4; }
        }
        __syncthreads();

        // -------- tracker GEMM --------
        {
            const int col = tid & 63, kc = tid >> 6;
            float acc[GPB];
#pragma unroll
            for (int b = 0; b < GPB; b++) acc[b] = 0.f;
            if (kc < 2) {
                const float* xb = (kc == 0) ? &sm->bt[0][0] : &sm->s1v[0][0];
                const float* wr = &sm->wK[kc * 128 * 64 + col];
                for (int kl = 0; kl < 128; kl += 4) {
                    float w0 = wr[(kl + 0) * 64], w1 = wr[(kl + 1) * 64];
                    float w2 = wr[(kl + 2) * 64], w3 = wr[(kl + 3) * 64];
#pragma unroll
                    for (int b = 0; b < GPB; b++) {
                        float4 x = *(const float4*)&xb[b * 256 + kl];
                        acc[b] += x.x * w0 + x.y * w1 + x.z * w2 + x.w * w3;
                    }
                }
            } else {
                const float* xb = (kc == 2) ? &sm->s2v[0][0] : &sm->h_s[rb][0][0];
                const int xs = (kc == 3) ? 128 : 256;
                const __half* wl = (kc == 2) ? &sm->wS2[col * 130] : &sm->wLat[col * 130];
                for (int kl = 0; kl < 128; kl += 4) {
                    float2 wf0 = __half22float2(*(const __half2*)&wl[kl]);
                    float2 wf1 = __half22float2(*(const __half2*)&wl[kl + 2]);
#pragma unroll
                    for (int b = 0; b < GPB; b++) {
                        float4 x = *(const float4*)&xb[b * xs + kl];
                        acc[b] += x.x * wf0.x + x.y * wf0.y + x.z * wf1.x + x.w * wf1.y;
                    }
                }
            }
            *(float4*)&sm->pt[kc * 512 + col * 8]     = make_float4(acc[0], acc[1], acc[2], acc[3]);
            *(float4*)&sm->pt[kc * 512 + col * 8 + 4] = make_float4(acc[4], acc[5], acc[6], acc[7]);
        }
        __syncthreads();

        // -------- cell + DSMEM h publish --------
        if (tid < 128) {
            const int jj = tid >> 3, b = tid & 7;
            float ga[4];
#pragma unroll
            for (int g = 0; g < 4; g++) {
                int c = g * 16 + jj;
                float v = sm->pt[c * 8 + b] + sm->pt[512 + c * 8 + b]
                        + sm->pt[1024 + c * 8 + b] + sm->pt[1536 + c * 8 + b];
                if (t > 0) v += sm->bias_lat[c];
                ga[g] = v;
            }
            float cn = sigf(ga[2]) * sm->c_s[b][jj] + sigf(ga[1]) * tanhf(ga[0]);
            float hn = sigf(ga[3]) * tanhf(cn);
            sm->c_s[b][jj] = cn;
            unsigned la = hsbase + (unsigned)(((wbuf * GPB + b) * 128 + (r << 4) + jj) * 4);
#pragma unroll
            for (int p = 0; p < CSZ; p++) st_remote_f32(la, p, hn);
        }
        __syncthreads();
        if (tid < CSZ) { fence_cluster(); arrive_peer(hbar, tid); }
        wait_parity_cluster(hbar, t & 1);

        // -------- loss (batch r, new h) --------
        if (tid < 32) {
            float p0 = 0.f, p1 = 0.f;
#pragma unroll
            for (int m = 0; m < 4; m++) {
                int j = tid + 32 * m;
                float h = sm->h_s[wbuf][r][j];
                p0 += h * sm->wtrans[2 * j];
                p1 += h * sm->wtrans[2 * j + 1];
            }
#pragma unroll
            for (int off = 16; off > 0; off >>= 1) {
                p0 += __shfl_xor_sync(0xffffffffu, p0, off);
                p1 += __shfl_xor_sync(0xffffffffu, p1, off);
            }
            if (tid == 0) {
                float l0 = p0 + sm->btr[0], l1 = p1 + sm->btr[1];
                float m = fmaxf(l0, l1);
                float lse = m + logf(expf(l0 - m) + expf(l1 - m));
                int trr = (sm->trbits[r][w5] >> b5) & 1;
                loss_reg += lse - ((trr == 0) ? l0 : l1);
            }
        }

        // -------- tree GEMM --------
        unsigned anyr = 0;
#pragma unroll
        for (int g = 0; g < GPB; g++) anyr |= (sm->trbits[g][w5] >> b5) & 1u;
        if (anyr && tid < 240) {
            const int kc = tid / 80, c = tid - kc * 80;
            const float* xb = (kc == 0) ? &sm->s2v[0][0]
                            : (kc == 1) ? &sm->s1v[0][0] : &sm->h_s[wbuf][0][0];
            const int xs = (kc == 2) ? 128 : 256;
            const __half* wr = &sm->wT[c * 386 + kc * 128];
            float acc[GPB];
#pragma unroll
            for (int b = 0; b < GPB; b++) acc[b] = 0.f;
            for (int kl = 0; kl < 128; kl += 4) {
                float2 wf0 = __half22float2(*(const __half2*)&wr[kl]);
                float2 wf1 = __half22float2(*(const __half2*)&wr[kl + 2]);
#pragma unroll
                for (int b = 0; b < GPB; b++) {
                    float4 x = *(const float4*)&xb[b * xs + kl];
                    acc[b] += x.x * wf0.x + x.y * wf0.y + x.z * wf1.x + x.w * wf1.y;
                }
            }
            *(float4*)&sm->pt[kc * 640 + c * 8]     = make_float4(acc[0], acc[1], acc[2], acc[3]);
            *(float4*)&sm->pt[kc * 640 + c * 8 + 4] = make_float4(acc[4], acc[5], acc[6], acc[7]);
        }
        __syncthreads();

        // -------- compose (reduce) + red publish + stack stcg --------
        if (tid < 128) {
            const int jj = tid >> 3, b = tid & 7;
            if ((sm->trbits[b][w5] >> b5) & 1) {
                const int j = (r << 4) + jj;
                float gg[5];
#pragma unroll
                for (int g = 0; g < 5; g++) {
                    int c = g * 16 + jj;
                    gg[g] = sm->pt[c * 8 + b] + sm->pt[640 + c * 8 + b]
                          + sm->pt[1280 + c * 8 + b] + sm->bias_red[c];
                }
                float cn = tanhf(gg[0]) * sigf(gg[1])
                         + sigf(gg[2]) * sm->s2v[b][128 + j]
                         + sigf(gg[3]) * sm->s1v[b][128 + j];
                float v1 = cn;
                float v0 = sigf(gg[4]) * tanhf(cn);
                const int wp = sm->sch_wp[t][b];
                __stcg(&stck[((size_t)b * Nn + wp) * 256 + j], v0);
                __stcg(&stck[((size_t)b * Nn + wp) * 256 + 128 + j], v1);
                unsigned la0 = redbase + (unsigned)((b * 256 + j) * 4);
                unsigned la1 = la0 + 128 * 4;
#pragma unroll
                for (int p = 0; p < CSZ; p++) {
                    st_remote_f32(la0, p, v0);
                    st_remote_f32(la1, p, v1);
                }
            }
        }
        // shift stack write (each rank writes its 32-dim slice of bt)
        if (tid < 64) {
            const int b = tid >> 3, q = (tid & 7) * 4;
            if (((sm->trbits[b][w5] >> b5) & 1) == 0) {
                const int wp = sm->sch_wp[t][b];
                __stcg((float4*)&stck[((size_t)b * Nn + wp) * 256 + r * 32 + q],
                       *(const float4*)&sm->bt[b][r * 32 + q]);
            }
        }
        __syncthreads();

        // -------- shift rename (thread-local) --------
        if (((sm->trbits[pb][w5] >> b5) & 1) == 0) {
            float4 s1a = *(const float4*)&sm->s1v[pb][pd];
            float4 s1b = *(const float4*)&sm->s1v[pb][pd + 4];
            float4 bta = *(const float4*)&sm->bt[pb][pd];
            float4 btb = *(const float4*)&sm->bt[pb][pd + 4];
            *(float4*)&sm->s2v[pb][pd]     = s1a;
            *(float4*)&sm->s2v[pb][pd + 4] = s1b;
            *(float4*)&sm->s1v[pb][pd]     = bta;
            *(float4*)&sm->s1v[pb][pd + 4] = btb;
            *(float4*)&sm->bt[pb][pd]      = bna;
            *(float4*)&sm->bt[pb][pd + 4]  = bnb;
        }
        if (tid < CSZ) { fence_cluster(); arrive_peer(sbar, tid); }
    }

    fence_cluster();
    asm volatile("barrier.cluster.arrive.aligned;" ::: "memory");
    asm volatile("barrier.cluster.wait.aligned;"   ::: "memory");

    if (tid < 64) {
        int fin = sm->fin_ptr[r];
        float4 v = __ldcg((const float4*)&stck[((size_t)r * Nn + fin) * 256 + tid * 4]);
        *(float4*)&out_final[(size_t)(b0 + r) * 256 + tid * 4] = v;
    }
    if (tid == 0) g_loss[b0 + r] = loss_reg;
}

// ---------------------------------------------------------------------------
// Kernel 3: loss reduction
// ---------------------------------------------------------------------------
__global__ void loss_kernel(float* __restrict__ out, int loss_idx)
{
    __shared__ float sl[128];
    int tid = threadIdx.x;
    sl[tid] = g_loss[tid];
    __syncthreads();
    for (int off = 64; off > 0; off >>= 1) {
        if (tid < off) sl[tid] += sl[tid + off];
        __syncthreads();
    }
    if (tid == 0) out[loss_idx] = sl[0] / (float)(Tt * Bb);
}

// ---------------------------------------------------------------------------
extern "C" void kernel_launch(void* const* d_in, const int* in_sizes, int n_in,
                              void* d_out, int out_size)
{
    const int*   tokens      = (const int*)  d_in[0];
    const int*   transitions = (const int*)  d_in[1];
    const float* embed_table = (const float*)d_in[2];
    const float* W_proj      = (const float*)d_in[3];
    const float* W_buf       = (const float*)d_in[4];
    const float* W_s1        = (const float*)d_in[5];
    const float* W_s2        = (const float*)d_in[6];
    const float* W_lat       = (const float*)d_in[7];
    const float* b_lat       = (const float*)d_in[8];
    const float* W_trans     = (const float*)d_in[9];
    const float* b_trans     = (const float*)d_in[10];
    const float* W_left      = (const float*)d_in[11];
    const float* W_right     = (const float*)d_in[12];
    const float* W_track     = (const float*)d_in[13];
    const float* b_reduce    = (const float*)d_in[14];
    float* out = (float*)d_out;

    static bool attr_done = false;
    if (!attr_done) {
        cudaFuncSetAttribute(spinn_seq,
                             cudaFuncAttributeMaxDynamicSharedMemorySize,
                             (int)sizeof(Smem));
        attr_done = true;
    }

    embed_kernel<<<(Bb * Nn) / 16, 256>>>(tokens, embed_table, W_proj);
    spinn_seq<<<Bb, 256, sizeof(Smem)>>>(transitions,
                                         W_buf, W_s1, W_s2, W_lat, b_lat,
                                         W_trans, b_trans,
                                         W_left, W_right, W_track, b_reduce,
                                         out);
    loss_kernel<<<1, 128>>>(out, out_size - 1);
}

// round 8
// speedup vs baseline: 2.7334x; 1.0091x over previous
#include <cuda_runtime.h>
#include <cuda_fp16.h>
#include <math.h>

#define Bb 128
#define Nn 128
#define Ee 300
#define Tt 255
#define CSZ 8
#define GPB 8

__device__ float g_buffer[Bb * Nn * 256];
__device__ float g_stack [Bb * Nn * 256];
__device__ float g_loss  [Bb];

__device__ __forceinline__ float sigf(float x) { return 1.0f / (1.0f + expf(-x)); }

__device__ __forceinline__ unsigned smem_u32(const void* p) {
    unsigned a;
    asm("{ .reg .u64 t; cvta.to.shared.u64 t, %1; cvt.u32.u64 %0, t; }" : "=r"(a) : "l"(p));
    return a;
}
__device__ __forceinline__ void fence_cluster() {
    asm volatile("fence.acq_rel.cluster;" ::: "memory");
}
// release-arrive on peer p's mbarrier: orders this CTA's prior (CTA-synced) writes
__device__ __forceinline__ void arrive_peer_rel(unsigned la, int p) {
    asm volatile("{ .reg .b32 ra; mapa.shared::cluster.u32 ra, %0, %1;"
                 " mbarrier.arrive.release.cluster.shared::cluster.b64 _, [ra]; }"
                 :: "r"(la), "r"(p) : "memory");
}
__device__ __forceinline__ void wait_parity_cluster(unsigned a, unsigned par) {
    asm volatile("{ .reg .pred P;\n"
                 "W_%=:\n"
                 " mbarrier.try_wait.parity.acquire.cluster.shared::cta.b64 P, [%0], %1, 0x989680;\n"
                 " @P bra D_%=;\n"
                 " bra W_%=;\n"
                 "D_%=:\n}"
                 :: "r"(a), "r"(par) : "memory");
}
__device__ __forceinline__ void st_remote_f32(unsigned la, int p, float v) {
    asm volatile("{ .reg .b32 ra; mapa.shared::cluster.u32 ra, %0, %1;"
                 " st.shared::cluster.f32 [ra], %2; }"
                 :: "r"(la), "r"(p), "f"(v) : "memory");
}

// ---------------------------------------------------------------------------
// Kernel 1: buffer[b,n,:] = embed_table[tokens[b,n]] @ W_proj
// ---------------------------------------------------------------------------
__global__ void __launch_bounds__(256) embed_kernel(
    const int*   __restrict__ tokens,
    const float* __restrict__ embed_table,
    const float* __restrict__ W_proj)
{
    __shared__ float se[16 * Ee];
    __shared__ int   stok[16];
    const int blk = blockIdx.x;
    const int tid = threadIdx.x;

    if (tid < 16) stok[tid] = tokens[blk * 16 + tid];
    __syncthreads();
    for (int idx = tid; idx < 16 * Ee; idx += 256) {
        int j = idx / Ee, e = idx - j * Ee;
        se[idx] = embed_table[(size_t)stok[j] * Ee + e];
    }
    __syncthreads();

    const int col = tid;
    float acc[16];
#pragma unroll
    for (int j = 0; j < 16; j++) acc[j] = 0.0f;
    for (int e = 0; e < Ee; e++) {
        float w = W_proj[e * 256 + col];
#pragma unroll
        for (int j = 0; j < 16; j++) acc[j] += se[j * Ee + e] * w;
    }
#pragma unroll
    for (int j = 0; j < 16; j++)
        g_buffer[(size_t)(blk * 16 + j) * 256 + col] = acc[j];
}

// ---------------------------------------------------------------------------
// Kernel 2: clustered scan, fence-free mbarrier sync, overlapped h exchange
// ---------------------------------------------------------------------------
struct __align__(16) Smem {
    float wK[2 * 128 * 64];         // W_buf, W_s1 fp32 [k][64]
    float h_s[2][GPB][128];
    float bt[GPB][256];
    float s1v[GPB][256];
    float s2v[GPB][256];
    float red_s[GPB][256];
    float pt[2560];                 // tracker 4*512 | tree L 640, R 640, T0 640, T1 640
    float c_s[GPB][16];
    float bias_lat[64];
    float bias_red[80];
    float wtrans[256];
    float btr[2];
    int   fin_ptr[GPB];
    unsigned long long mbar[2];     // [0]=hbar, [1]=sbar
    __half wS2[64 * 130];
    __half wLat[64 * 130];
    __half wT[80 * 386];            // [c][kc*128+k]
    unsigned trbits[GPB][8];
    unsigned char sch_wp[Tt][GPB];
    unsigned char sch_bt[Tt + 1][GPB];
    signed char   sch_rf[Tt][GPB];
};

__global__ void __launch_bounds__(256, 1) __cluster_dims__(CSZ, 1, 1)
spinn_seq(
    const int*   __restrict__ transitions,
    const float* __restrict__ W_buf,  const float* __restrict__ W_s1,
    const float* __restrict__ W_s2,   const float* __restrict__ W_lat,
    const float* __restrict__ b_lat,
    const float* __restrict__ W_trans,const float* __restrict__ b_trans,
    const float* __restrict__ W_left, const float* __restrict__ W_right,
    const float* __restrict__ W_track,const float* __restrict__ b_reduce,
    float* __restrict__ out_final)
{
    extern __shared__ char smraw[];
    Smem* sm = (Smem*)smraw;
    const int tid = threadIdx.x;
    const int r   = blockIdx.x & (CSZ - 1);
    const int b0  = blockIdx.x & ~(CSZ - 1);

    float*       stck = g_stack  + (size_t)b0 * Nn * 256;
    const float* buf  = g_buffer + (size_t)b0 * Nn * 256;

    // ---------------- init ----------------
    for (int idx = tid; idx < 2 * 128 * 64; idx += 256) {
        int k = idx >> 6, c = idx & 63;
        int G = ((c >> 4) << 7) + (r << 4) + (c & 15);
        sm->wK[idx] = (k < 128) ? W_buf[k * 512 + G] : W_s1[(k - 128) * 512 + G];
    }
    for (int idx = tid; idx < 64 * 128; idx += 256) {
        int c = idx >> 7, k = idx & 127;
        int G = ((c >> 4) << 7) + (r << 4) + (c & 15);
        sm->wS2 [c * 130 + k] = __float2half(W_s2 [k * 512 + G]);
        sm->wLat[c * 130 + k] = __float2half(W_lat[k * 512 + G]);
    }
    for (int idx = tid; idx < 80 * 384; idx += 256) {
        int c = idx / 384, k = idx - c * 384;
        int G = ((c >> 4) << 7) + (r << 4) + (c & 15);
        float w = (k < 128) ? W_left[k * 640 + G]
                : (k < 256) ? W_right[(k - 128) * 640 + G]
                            : W_track[(k - 256) * 640 + G];
        sm->wT[c * 386 + k] = __float2half(w);
    }
    if (tid < 64) sm->bias_lat[tid] = b_lat[((tid >> 4) << 7) + (r << 4) + (tid & 15)];
    if (tid < 80) sm->bias_red[tid] = b_reduce[((tid >> 4) << 7) + (r << 4) + (tid & 15)];
    sm->wtrans[tid] = W_trans[tid];
    if (tid < 2) sm->btr[tid] = b_trans[tid];
    if (tid < 64) {
        int g = tid >> 3, w = tid & 7;
        unsigned bits = 0;
        for (int i = 0; i < 32; i++) {
            int tt = w * 32 + i;
            if (tt < Tt) bits |= (unsigned)(transitions[(b0 + g) * Tt + tt] & 1) << i;
        }
        sm->trbits[g][w] = bits;
    }
    for (int i = tid; i < 2 * GPB * 128; i += 256) ((float*)sm->h_s)[i] = 0.f;
    for (int i = tid; i < GPB * 16;  i += 256) ((float*)sm->c_s)[i] = 0.f;
    for (int i = tid; i < GPB * 256; i += 256) {
        ((float*)sm->s1v)[i] = 0.f;
        ((float*)sm->s2v)[i] = 0.f;
        ((float*)sm->red_s)[i] = 0.f;
    }
    for (int i = tid; i < GPB * 64; i += 256) {
        int b = i >> 6, q = (i & 63) * 4;
        *(float4*)&sm->bt[b][q] = *(const float4*)&buf[((size_t)b * Nn) * 256 + q];
    }
    if (tid == 0) {
        unsigned mb = smem_u32(&sm->mbar[0]);
        asm volatile("mbarrier.init.shared.b64 [%0], %1;" :: "r"(mb),   "r"(CSZ) : "memory");
        asm volatile("mbarrier.init.shared.b64 [%0], %1;" :: "r"(mb+8), "r"(CSZ) : "memory");
    }
    __syncthreads();

    if (tid < GPB) {
        const int g = tid;
        int p = 0, bp = 0;
        for (int t = 0; t < Tt; t++) {
            int trv = (sm->trbits[g][t >> 5] >> (t & 31)) & 1;
            int bi = (bp < Nn - 1) ? bp : (Nn - 1);
            sm->sch_bt[t][g] = (unsigned char)bi;
            int wp = trv ? ((p - 2 >= 0) ? p - 2 : 0) : p;
            if (wp > Nn - 1) wp = Nn - 1;
            sm->sch_wp[t][g] = (unsigned char)wp;
            sm->sch_rf[t][g] = (signed char)((trv && p >= 3) ? (p - 3) : -1);
            p  += trv ? -1 : 1;
            bp += trv ? 0 : 1;
        }
        sm->sch_bt[Tt][g] = sm->sch_bt[Tt - 1][g];
        int fin = (p - 1 >= 0) ? p - 1 : 0;
        sm->fin_ptr[g] = (fin > Nn - 1) ? Nn - 1 : fin;
    }
    __syncthreads();
    asm volatile("barrier.cluster.arrive.aligned;" ::: "memory");
    asm volatile("barrier.cluster.wait.aligned;"   ::: "memory");

    const unsigned hbar    = smem_u32(&sm->mbar[0]);
    const unsigned sbar    = hbar + 8;
    const unsigned hsbase  = smem_u32(&sm->h_s[0][0][0]);
    const unsigned redbase = smem_u32(&sm->red_s[0][0]);

    const int pb = tid >> 5;
    const int pd = (tid & 31) * 8;
    const float4 z4 = make_float4(0.f, 0.f, 0.f, 0.f);
    float4 rfa = z4, rfb = z4;
    float4 bna = z4, bnb = z4;
    float loss_reg = 0.f;

    for (int t = 0; t < Tt; t++) {
        const int w5 = t >> 5, b5 = t & 31;
        const int rb = t & 1, wbuf = 1 - rb;

        // ---- P0: prefetch (before the wait; rows are >=3 steps old) ----
        {
            int nbt = sm->sch_bt[t + 1][pb];
            const float* bsrc = &buf[((size_t)pb * Nn + nbt) * 256 + pd];
            bna = __ldg((const float4*)bsrc);
            bnb = __ldg((const float4*)(bsrc + 4));
            int rfi = sm->sch_rf[t][pb];
            if (rfi >= 0) {
                const float* rsrc = &stck[((size_t)pb * Nn + rfi) * 256 + pd];
                rfa = __ldcg((const float4*)rsrc);
                rfb = __ldcg((const float4*)(rsrc + 4));
            } else { rfa = z4; rfb = z4; }
        }
        if (t > 0) {
            wait_parity_cluster(sbar, (t - 1) & 1);
            if ((sm->trbits[pb][(t - 1) >> 5] >> ((t - 1) & 31)) & 1) {
                float4 r0 = *(const float4*)&sm->red_s[pb][pd];
                float4 r1 = *(const float4*)&sm->red_s[pb][pd + 4];
                *(float4*)&sm->s1v[pb][pd]     = r0;
                *(float4*)&sm->s1v[pb][pd + 4] = r1;
                *(float4*)&sm->s2v[pb][pd]     = rfa;
                *(float4*)&sm->s2v[pb][pd + 4] = rfb;
            }
        }
        __syncthreads();

        // ---- P1: tracker GEMM ----
        {
            const int col = tid & 63, kc = tid >> 6;
            float acc[GPB];
#pragma unroll
            for (int b = 0; b < GPB; b++) acc[b] = 0.f;
            if (kc < 2) {
                const float* xb = (kc == 0) ? &sm->bt[0][0] : &sm->s1v[0][0];
                const float* wr = &sm->wK[kc * 128 * 64 + col];
                for (int kl = 0; kl < 128; kl += 4) {
                    float w0 = wr[(kl + 0) * 64], w1 = wr[(kl + 1) * 64];
                    float w2 = wr[(kl + 2) * 64], w3 = wr[(kl + 3) * 64];
#pragma unroll
                    for (int b = 0; b < GPB; b++) {
                        float4 x = *(const float4*)&xb[b * 256 + kl];
                        acc[b] += x.x * w0 + x.y * w1 + x.z * w2 + x.w * w3;
                    }
                }
            } else {
                const float* xb = (kc == 2) ? &sm->s2v[0][0] : &sm->h_s[rb][0][0];
                const int xs = (kc == 3) ? 128 : 256;
                const __half* wl = (kc == 2) ? &sm->wS2[col * 130] : &sm->wLat[col * 130];
                for (int kl = 0; kl < 128; kl += 4) {
                    float2 wf0 = __half22float2(*(const __half2*)&wl[kl]);
                    float2 wf1 = __half22float2(*(const __half2*)&wl[kl + 2]);
#pragma unroll
                    for (int b = 0; b < GPB; b++) {
                        float4 x = *(const float4*)&xb[b * xs + kl];
                        acc[b] += x.x * wf0.x + x.y * wf0.y + x.z * wf1.x + x.w * wf1.y;
                    }
                }
            }
            *(float4*)&sm->pt[kc * 512 + col * 8]     = make_float4(acc[0], acc[1], acc[2], acc[3]);
            *(float4*)&sm->pt[kc * 512 + col * 8 + 4] = make_float4(acc[4], acc[5], acc[6], acc[7]);
        }
        __syncthreads();

        // ---- P2: cell + DSMEM h publish ----
        if (tid < 128) {
            const int jj = tid >> 3, b = tid & 7;
            float ga[4];
#pragma unroll
            for (int g = 0; g < 4; g++) {
                int c = g * 16 + jj;
                float v = sm->pt[c * 8 + b] + sm->pt[512 + c * 8 + b]
                        + sm->pt[1024 + c * 8 + b] + sm->pt[1536 + c * 8 + b];
                if (t > 0) v += sm->bias_lat[c];
                ga[g] = v;
            }
            float cn = sigf(ga[2]) * sm->c_s[b][jj] + sigf(ga[1]) * tanhf(ga[0]);
            float hn = sigf(ga[3]) * tanhf(cn);
            sm->c_s[b][jj] = cn;
            unsigned la = hsbase + (unsigned)(((wbuf * GPB + b) * 128 + (r << 4) + jj) * 4);
#pragma unroll
            for (int p = 0; p < CSZ; p++) st_remote_f32(la, p, hn);
        }
        __syncthreads();

        unsigned anyr = 0;
#pragma unroll
        for (int g = 0; g < GPB; g++) anyr |= (sm->trbits[g][w5] >> b5) & 1u;

        // ---- P3: release-arrive hbar, then tree L/R slices (overlap) ----
        if (tid < CSZ) arrive_peer_rel(hbar, tid);
        if (anyr && tid < 160) {
            const int kc = tid / 80, c = tid - kc * 80;   // 0=left(s2), 1=right(s1)
            const float* xb = (kc == 0) ? &sm->s2v[0][0] : &sm->s1v[0][0];
            const __half* wr = &sm->wT[c * 386 + kc * 128];
            float acc[GPB];
#pragma unroll
            for (int b = 0; b < GPB; b++) acc[b] = 0.f;
            for (int kl = 0; kl < 128; kl += 4) {
                float2 wf0 = __half22float2(*(const __half2*)&wr[kl]);
                float2 wf1 = __half22float2(*(const __half2*)&wr[kl + 2]);
#pragma unroll
                for (int b = 0; b < GPB; b++) {
                    float4 x = *(const float4*)&xb[b * 256 + kl];
                    acc[b] += x.x * wf0.x + x.y * wf0.y + x.z * wf1.x + x.w * wf1.y;
                }
            }
            *(float4*)&sm->pt[kc * 640 + c * 8]     = make_float4(acc[0], acc[1], acc[2], acc[3]);
            *(float4*)&sm->pt[kc * 640 + c * 8 + 4] = make_float4(acc[4], acc[5], acc[6], acc[7]);
        }

        // ---- P4: wait hbar, track slice (k halves) + loss ----
        wait_parity_cluster(hbar, t & 1);
        if (anyr && tid < 160) {
            const int half = tid / 80, c = tid - half * 80;
            const float* xb = &sm->h_s[wbuf][0][0];
            const __half* wr = &sm->wT[c * 386 + 256 + half * 64];
            const int k0 = half * 64;
            float acc[GPB];
#pragma unroll
            for (int b = 0; b < GPB; b++) acc[b] = 0.f;
            for (int kl = 0; kl < 64; kl += 4) {
                float2 wf0 = __half22float2(*(const __half2*)&wr[kl]);
                float2 wf1 = __half22float2(*(const __half2*)&wr[kl + 2]);
#pragma unroll
                for (int b = 0; b < GPB; b++) {
                    float4 x = *(const float4*)&xb[b * 128 + k0 + kl];
                    acc[b] += x.x * wf0.x + x.y * wf0.y + x.z * wf1.x + x.w * wf1.y;
                }
            }
            *(float4*)&sm->pt[1280 + half * 640 + c * 8]     = make_float4(acc[0], acc[1], acc[2], acc[3]);
            *(float4*)&sm->pt[1280 + half * 640 + c * 8 + 4] = make_float4(acc[4], acc[5], acc[6], acc[7]);
        }
        if (tid >= 224) {
            const int l = tid - 224;
            float p0 = 0.f, p1 = 0.f;
#pragma unroll
            for (int m = 0; m < 4; m++) {
                int j = l + 32 * m;
                float h = sm->h_s[wbuf][r][j];
                p0 += h * sm->wtrans[2 * j];
                p1 += h * sm->wtrans[2 * j + 1];
            }
#pragma unroll
            for (int off = 16; off > 0; off >>= 1) {
                p0 += __shfl_xor_sync(0xffffffffu, p0, off);
                p1 += __shfl_xor_sync(0xffffffffu, p1, off);
            }
            if (l == 0) {
                float l0 = p0 + sm->btr[0], l1 = p1 + sm->btr[1];
                float m = fmaxf(l0, l1);
                float lse = m + logf(expf(l0 - m) + expf(l1 - m));
                int trr = (sm->trbits[r][w5] >> b5) & 1;
                loss_reg += lse - ((trr == 0) ? l0 : l1);
            }
        }
        __syncthreads();

        // ---- P5: compose + red publish (tid<128) || shift stack write (tid 128-191) ----
        if (tid < 128) {
            const int jj = tid >> 3, b = tid & 7;
            if ((sm->trbits[b][w5] >> b5) & 1) {
                const int j = (r << 4) + jj;
                float gg[5];
#pragma unroll
                for (int g = 0; g < 5; g++) {
                    int c = g * 16 + jj;
                    gg[g] = sm->pt[c * 8 + b] + sm->pt[640 + c * 8 + b]
                          + sm->pt[1280 + c * 8 + b] + sm->pt[1920 + c * 8 + b]
                          + sm->bias_red[c];
                }
                float cn = tanhf(gg[0]) * sigf(gg[1])
                         + sigf(gg[2]) * sm->s2v[b][128 + j]
                         + sigf(gg[3]) * sm->s1v[b][128 + j];
                float v1 = cn;
                float v0 = sigf(gg[4]) * tanhf(cn);
                const int wp = sm->sch_wp[t][b];
                __stcg(&stck[((size_t)b * Nn + wp) * 256 + j], v0);
                __stcg(&stck[((size_t)b * Nn + wp) * 256 + 128 + j], v1);
                unsigned la0 = redbase + (unsigned)((b * 256 + j) * 4);
                unsigned la1 = la0 + 128 * 4;
#pragma unroll
                for (int p = 0; p < CSZ; p++) {
                    st_remote_f32(la0, p, v0);
                    st_remote_f32(la1, p, v1);
                }
            }
        } else if (tid < 192) {
            const int u = tid - 128;
            const int b = u >> 3, q = (u & 7) * 4;
            if (((sm->trbits[b][w5] >> b5) & 1) == 0) {
                const int wp = sm->sch_wp[t][b];
                __stcg((float4*)&stck[((size_t)b * Nn + wp) * 256 + r * 32 + q],
                       *(const float4*)&sm->bt[b][r * 32 + q]);
            }
        }
        __syncthreads();

        // ---- P6: shift rename (local) + release-arrive sbar ----
        if (((sm->trbits[pb][w5] >> b5) & 1) == 0) {
            float4 s1a = *(const float4*)&sm->s1v[pb][pd];
            float4 s1b = *(const float4*)&sm->s1v[pb][pd + 4];
            float4 bta = *(const float4*)&sm->bt[pb][pd];
            float4 btb = *(const float4*)&sm->bt[pb][pd + 4];
            *(float4*)&sm->s2v[pb][pd]     = s1a;
            *(float4*)&sm->s2v[pb][pd + 4] = s1b;
            *(float4*)&sm->s1v[pb][pd]     = bta;
            *(float4*)&sm->s1v[pb][pd + 4] = btb;
            *(float4*)&sm->bt[pb][pd]      = bna;
            *(float4*)&sm->bt[pb][pd + 4]  = bnb;
        }
        if (tid < CSZ) arrive_peer_rel(sbar, tid);
    }

    fence_cluster();
    asm volatile("barrier.cluster.arrive.aligned;" ::: "memory");
    asm volatile("barrier.cluster.wait.aligned;"   ::: "memory");

    if (tid < 64) {
        int fin = sm->fin_ptr[r];
        float4 v = __ldcg((const float4*)&stck[((size_t)r * Nn + fin) * 256 + tid * 4]);
        *(float4*)&out_final[(size_t)(b0 + r) * 256 + tid * 4] = v;
    }
    if (tid == 224) g_loss[b0 + r] = loss_reg;   // loss lives in warp 7 lane 0
}

// ---------------------------------------------------------------------------
// Kernel 3: loss reduction
// ---------------------------------------------------------------------------
__global__ void loss_kernel(float* __restrict__ out, int loss_idx)
{
    __shared__ float sl[128];
    int tid = threadIdx.x;
    sl[tid] = g_loss[tid];
    __syncthreads();
    for (int off = 64; off > 0; off >>= 1) {
        if (tid < off) sl[tid] += sl[tid + off];
        __syncthreads();
    }
    if (tid == 0) out[loss_idx] = sl[0] / (float)(Tt * Bb);
}

// ---------------------------------------------------------------------------
extern "C" void kernel_launch(void* const* d_in, const int* in_sizes, int n_in,
                              void* d_out, int out_size)
{
    const int*   tokens      = (const int*)  d_in[0];
    const int*   transitions = (const int*)  d_in[1];
    const float* embed_table = (const float*)d_in[2];
    const float* W_proj      = (const float*)d_in[3];
    const float* W_buf       = (const float*)d_in[4];
    const float* W_s1        = (const float*)d_in[5];
    const float* W_s2        = (const float*)d_in[6];
    const float* W_lat       = (const float*)d_in[7];
    const float* b_lat       = (const float*)d_in[8];
    const float* W_trans     = (const float*)d_in[9];
    const float* b_trans     = (const float*)d_in[10];
    const float* W_left      = (const float*)d_in[11];
    const float* W_right     = (const float*)d_in[12];
    const float* W_track     = (const float*)d_in[13];
    const float* b_reduce    = (const float*)d_in[14];
    float* out = (float*)d_out;

    static bool attr_done = false;
    if (!attr_done) {
        cudaFuncSetAttribute(spinn_seq,
                             cudaFuncAttributeMaxDynamicSharedMemorySize,
                             (int)sizeof(Smem));
        attr_done = true;
    }

    embed_kernel<<<(Bb * Nn) / 16, 256>>>(tokens, embed_table, W_proj);
    spinn_seq<<<Bb, 256, sizeof(Smem)>>>(transitions,
                                         W_buf, W_s1, W_s2, W_lat, b_lat,
                                         W_trans, b_trans,
                                         W_left, W_right, W_track, b_reduce,
                                         out);
    loss_kernel<<<1, 128>>>(out, out_size - 1);
}